// round 4
// baseline (speedup 1.0000x reference)
#include <cuda_runtime.h>
#include <cuda_fp16.h>
#include <cstdint>
#include <math.h>

// ---------------------------------------------------------------------------
// SambaMixerBlock: B=8, S=D=1024, N=16, DCONV=4, EXPAND=2 -> DI=2048, DT_RANK=64
// Round 4: pre-split fp16 hi/lo operands + cp.async 3-stage pipelined HMMA GEMM,
//          split-K x_proj, software-pipelined scan.
// ---------------------------------------------------------------------------

#define BSZ   8
#define SEQ   1024
#define DM    1024
#define DI_   2048
#define NST   16
#define DTR   64
#define XD    96
#define ROWS  (BSZ*SEQ)
#define KSP   4                      // x_proj split-K factor

// fp32 scratch
__device__ float g_xz  [(size_t)ROWS * 2 * DI_];
__device__ float g_xh  [(size_t)ROWS * DI_];
__device__ float g_dt  [(size_t)ROWS * DI_];
__device__ float g_xdbl[(size_t)ROWS * XD];
__device__ float g_xpart[(size_t)KSP * ROWS * XD];
__device__ float g_res1[(size_t)ROWS * DM];
__device__ float g_hmix[(size_t)ROWS * DM];
__device__ float g_outm[(size_t)ROWS * DM];
// fp16 hi/lo operand scratch
__device__ __half g_ah[(size_t)ROWS * DI_];
__device__ __half g_al[(size_t)ROWS * DI_];
__device__ __half g_bh[(size_t)2 * DI_ * DM];
__device__ __half g_bl[(size_t)2 * DI_ * DM];
__device__ __half g_dh[(size_t)ROWS * DTR];
__device__ __half g_dl[(size_t)ROWS * DTR];

// ---------------------------------------------------------------------------
__device__ __forceinline__ void split1(float v, __half* hi, __half* lo)
{
    __half h = __float2half_rn(v);
    *hi = h;
    *lo = __float2half_rn(v - __half2float(h));
}

__device__ __forceinline__ void cpa16(uint32_t d, const void* s)
{
    asm volatile("cp.async.cg.shared.global [%0], [%1], 16;" :: "r"(d), "l"(s));
}
__device__ __forceinline__ void cpa16z(uint32_t d, const void* s, bool ok)
{
    int sz = ok ? 16 : 0;
    asm volatile("cp.async.cg.shared.global [%0], [%1], 16, %2;"
                 :: "r"(d), "l"(s), "r"(sz));
}
#define CP_COMMIT() asm volatile("cp.async.commit_group;" ::: "memory")
#define CP_WAIT1()  asm volatile("cp.async.wait_group 1;" ::: "memory")

__device__ __forceinline__ void mma16816(float* d, const uint32_t* a, const uint32_t* b)
{
    asm volatile(
        "mma.sync.aligned.m16n8k16.row.col.f32.f16.f16.f32 "
        "{%0,%1,%2,%3}, {%4,%5,%6,%7}, {%8,%9}, {%0,%1,%2,%3};"
        : "+f"(d[0]), "+f"(d[1]), "+f"(d[2]), "+f"(d[3])
        : "r"(a[0]), "r"(a[1]), "r"(a[2]), "r"(a[3]), "r"(b[0]), "r"(b[1]));
}

// ---------------------------------------------------------------------------
// Pipelined HMMA GEMM: C = A(M,K) * B(N,K)^T, fp16 hi/lo x3, fp32 acc.
// CTA 128 x TN, BK=32, 3-stage cp.async. Split-K via blockIdx.z (partials).
// smem row stride 80B -> conflict-free fragment LDS.
// EPI==1: C = softplus(C + bias)
// ---------------------------------------------------------------------------
template<int TN, int EPI>
__global__ __launch_bounds__(256, 1) void gemm_cp(
    const __half* __restrict__ Ah, const __half* __restrict__ Al, int lda,
    const __half* __restrict__ Bh, const __half* __restrict__ Bl,
    const float* __restrict__ bias, float* __restrict__ Cbase,
    int M, int Nsz, int Kfull, int Ksub)
{
    constexpr int ABY = 128 * 80;
    constexpr int BBY = TN * 80;
    constexpr int STG = 2 * ABY + 2 * BBY;
    constexpr int JN  = TN / 32;

    extern __shared__ __align__(16) char smem[];
    const uint32_t sb0 = (uint32_t)__cvta_generic_to_shared(smem);

    const int tid = threadIdx.x, wid = tid >> 5, lid = tid & 31;
    const int bm = blockIdx.y * 128, bn = blockIdx.x * TN;
    const int koff = blockIdx.z * Ksub;
    float* C = Cbase + (size_t)blockIdx.z * M * Nsz;
    const int wm = (wid & 1) * 64, wn = (wid >> 1) * (TN / 4);
    const int g = lid >> 2, t4 = lid & 3;
    const int S = Ksub >> 5;

    auto issue = [&](int s) {
        const int k0 = koff + (s << 5);
        const uint32_t st = sb0 + (s % 3) * STG;
#pragma unroll
        for (int i = 0; i < 2; i++) {
            const int id = tid + i * 256, row = id >> 2, q = id & 3;
            const size_t go = (size_t)(bm + row) * lda + k0 + q * 8;
            cpa16(st + row * 80 + q * 16, Ah + go);
            cpa16(st + ABY + row * 80 + q * 16, Al + go);
        }
#pragma unroll
        for (int i = 0; i < TN / 64; i++) {
            const int id = tid + i * 256, row = id >> 2, q = id & 3;
            const bool ok = (bn + row) < Nsz;
            const int r2 = ok ? (bn + row) : 0;
            const size_t go = (size_t)r2 * Kfull + k0 + q * 8;
            cpa16z(st + 2 * ABY + row * 80 + q * 16, Bh + go, ok);
            cpa16z(st + 2 * ABY + BBY + row * 80 + q * 16, Bl + go, ok);
        }
    };

    float acc[4][JN][4];
#pragma unroll
    for (int i = 0; i < 4; i++)
#pragma unroll
        for (int j = 0; j < JN; j++)
#pragma unroll
            for (int c = 0; c < 4; c++) acc[i][j][c] = 0.f;

    issue(0); CP_COMMIT();
    if (S > 1) issue(1);
    CP_COMMIT();

    for (int s = 0; s < S; s++) {
        CP_WAIT1();
        __syncthreads();
        if (s + 2 < S) issue(s + 2);
        CP_COMMIT();

        const char* sb = smem + (s % 3) * STG;
#pragma unroll
        for (int kk = 0; kk < 2; kk++) {
            const int cb = kk * 32 + t4 * 4;
            uint32_t ah[4][4], al[4][4];
#pragma unroll
            for (int i = 0; i < 4; i++) {
                const char* pa = sb + (wm + i * 16 + g) * 80 + cb;
                ah[i][0] = *(const uint32_t*)(pa);
                ah[i][1] = *(const uint32_t*)(pa + 8 * 80);
                ah[i][2] = *(const uint32_t*)(pa + 16);
                ah[i][3] = *(const uint32_t*)(pa + 8 * 80 + 16);
                const char* pl = pa + ABY;
                al[i][0] = *(const uint32_t*)(pl);
                al[i][1] = *(const uint32_t*)(pl + 8 * 80);
                al[i][2] = *(const uint32_t*)(pl + 16);
                al[i][3] = *(const uint32_t*)(pl + 8 * 80 + 16);
            }
#pragma unroll
            for (int j = 0; j < JN; j++) {
                const char* pb = sb + 2 * ABY + (wn + j * 8 + g) * 80 + cb;
                uint32_t bh[2], bl[2];
                bh[0] = *(const uint32_t*)(pb);
                bh[1] = *(const uint32_t*)(pb + 16);
                bl[0] = *(const uint32_t*)(pb + BBY);
                bl[1] = *(const uint32_t*)(pb + BBY + 16);
#pragma unroll
                for (int i = 0; i < 4; i++) {
                    mma16816(acc[i][j], ah[i], bh);
                    mma16816(acc[i][j], al[i], bh);
                    mma16816(acc[i][j], ah[i], bl);
                }
            }
        }
    }

#pragma unroll
    for (int i = 0; i < 4; i++) {
        const int r0 = bm + wm + i * 16 + g;
#pragma unroll
        for (int j = 0; j < JN; j++) {
            const int c = bn + wn + j * 8 + t4 * 2;
            if (c < Nsz) {
                float v0 = acc[i][j][0], v1 = acc[i][j][1];
                float v2 = acc[i][j][2], v3 = acc[i][j][3];
                if (EPI == 1) {
                    const float b0 = bias[c], b1 = bias[c + 1];
                    v0 += b0; v1 += b1; v2 += b0; v3 += b1;
                    v0 = (v0 > 20.f) ? v0 : log1pf(__expf(v0));
                    v1 = (v1 > 20.f) ? v1 : log1pf(__expf(v1));
                    v2 = (v2 > 20.f) ? v2 : log1pf(__expf(v2));
                    v3 = (v3 > 20.f) ? v3 : log1pf(__expf(v3));
                }
                *(float2*)(C + (size_t)r0 * Nsz + c)       = make_float2(v0, v1);
                *(float2*)(C + (size_t)(r0 + 8) * Nsz + c) = make_float2(v2, v3);
            }
        }
    }
}

// ---------------------------------------------------------------------------
// weight split: fp32 -> fp16 hi/lo
// ---------------------------------------------------------------------------
__global__ __launch_bounds__(256) void split_w_kernel(
    const float* __restrict__ w, __half* __restrict__ hi, __half* __restrict__ lo, int n)
{
    const int i = blockIdx.x * 256 + threadIdx.x;
    if (i < n) split1(w[i], hi + i, lo + i);
}

// ---------------------------------------------------------------------------
// x_proj split-K reduce: xdbl = sum partials; also emit dt-slice hi/lo
// ---------------------------------------------------------------------------
__global__ __launch_bounds__(256) void reduce_xproj_kernel(
    const float* __restrict__ part, float* __restrict__ xdbl,
    __half* __restrict__ dh, __half* __restrict__ dl)
{
    const size_t n1 = (size_t)ROWS * XD;
    const size_t i = (size_t)blockIdx.x * 256 + threadIdx.x;
    float s = part[i] + part[i + n1] + part[i + 2 * n1] + part[i + 3 * n1];
    xdbl[i] = s;
    const int col = (int)(i % XD);
    if (col < DTR) {
        const size_t row = i / XD;
        split1(s, dh + row * DTR + col, dl + row * DTR + col);
    }
}

// ---------------------------------------------------------------------------
// Depthwise causal conv + bias + SiLU -> xh fp32 AND hi/lo halves
// ---------------------------------------------------------------------------
__global__ __launch_bounds__(256) void conv_silu_kernel(
    const float* __restrict__ xz, const float* __restrict__ w,
    const float* __restrict__ bias, float* __restrict__ xh,
    __half* __restrict__ oh, __half* __restrict__ ol)
{
    const long i = (long)blockIdx.x * 256 + threadIdx.x;
    const int  d = (int)(i & (DI_ - 1));
    const long bl = i >> 11;
    const int  l = (int)(bl & (SEQ - 1));
    const long b = bl >> 10;

    const float* base = xz + ((size_t)b * SEQ) * (2 * DI_) + d;
    float acc = bias[d];
    const float w0 = w[d * 4 + 0], w1 = w[d * 4 + 1], w2 = w[d * 4 + 2], w3 = w[d * 4 + 3];
    if (l >= 3) acc += w0 * base[(size_t)(l - 3) * (2 * DI_)];
    if (l >= 2) acc += w1 * base[(size_t)(l - 2) * (2 * DI_)];
    if (l >= 1) acc += w2 * base[(size_t)(l - 1) * (2 * DI_)];
    acc += w3 * base[(size_t)l * (2 * DI_)];
    acc = acc / (1.f + __expf(-acc));
    xh[i] = acc;
    split1(acc, oh + i, ol + i);
}

// ---------------------------------------------------------------------------
// Selective scan, software-pipelined. Writes y directly as hi/lo halves.
// ---------------------------------------------------------------------------
__global__ __launch_bounds__(128) void scan_kernel(
    const float* __restrict__ dtb, const float* __restrict__ xh,
    const float* __restrict__ xdbl, const float* __restrict__ xz,
    const float* __restrict__ A_log, const float* __restrict__ Dp,
    __half* __restrict__ yh, __half* __restrict__ yl)
{
    const int b = blockIdx.y;
    const int d = blockIdx.x * 128 + threadIdx.x;
    const int tid = threadIdx.x;

    float A[NST], h[NST];
#pragma unroll
    for (int n = 0; n < NST; n++) {
        A[n] = -__expf(A_log[d * NST + n]);
        h[n] = 0.f;
    }
    const float dval = Dp[d];

    __shared__ float sB[2][NST], sC[2][NST];
    const size_t rowbase = (size_t)b * SEQ;

    // prologue: fill both B/C parities (l=0,1), prefetch l=2 into reg
    if (tid < 2 * NST) {
        for (int p = 0; p < 2; p++) {
            float v = xdbl[(rowbase + p) * XD + DTR + tid];
            if (tid < NST) sB[p][tid] = v; else sC[p][tid - NST] = v;
        }
    }
    float bc_next = 0.f;
    if (tid < 2 * NST) bc_next = xdbl[(rowbase + 2) * XD + DTR + tid];

    float dq[2], xq[2], zq[2];
#pragma unroll
    for (int p = 0; p < 2; p++) {
        const size_t idx = (rowbase + p) * DI_ + d;
        dq[p] = dtb[idx];
        xq[p] = xh[idx];
        zq[p] = xz[(rowbase + p) * (2 * DI_) + DI_ + d];
    }
    __syncthreads();

    for (int l = 0; l < SEQ; l++) {
        const int par = l & 1;
        const float dtv = dq[par], xv = xq[par], zv = zq[par];

        // prefetch l+2 into the ring slot just freed
        const int lp = (l + 2 < SEQ) ? l + 2 : SEQ - 1;
        const size_t idx2 = (rowbase + lp) * DI_ + d;
        dq[par] = dtb[idx2];
        xq[par] = xh[idx2];
        zq[par] = xz[(rowbase + lp) * (2 * DI_) + DI_ + d];

        const float dx = dtv * xv;
        float acc = 0.f;
#pragma unroll
        for (int n = 0; n < NST; n++) {
            h[n] = __expf(dtv * A[n]) * h[n] + dx * sB[par][n];
            acc += h[n] * sC[par][n];
        }
        acc += xv * dval;
        acc *= zv / (1.f + __expf(-zv));

        const size_t oidx = (rowbase + l) * DI_ + d;
        split1(acc, yh + oidx, yl + oidx);

        __syncthreads();
        if (tid < 2 * NST) {
            if (tid < NST) sB[par][tid] = bc_next; else sC[par][tid - NST] = bc_next;
            const int lq = (l + 3 < SEQ) ? l + 3 : SEQ - 1;
            bc_next = xdbl[(rowbase + lq) * XD + DTR + tid];
        }
    }
}

// ---------------------------------------------------------------------------
__device__ __forceinline__ float block_sum256(float v)
{
    __shared__ float red[8];
    const int lane = threadIdx.x & 31, w = threadIdx.x >> 5;
#pragma unroll
    for (int o = 16; o; o >>= 1) v += __shfl_xor_sync(0xffffffffu, v, o);
    if (!lane) red[w] = v;
    __syncthreads();
    if (w == 0) {
        v = (lane < 8) ? red[lane] : 0.f;
#pragma unroll
        for (int o = 4; o; o >>= 1) v += __shfl_xor_sync(0xffffffffu, v, o);
        if (!lane) red[0] = v;
    }
    __syncthreads();
    return red[0];
}

// res1 + rmsnorm + softmax-mix -> hi/lo halves (GEMM A operand)
__global__ __launch_bounds__(256) void rms_mix_tm_kernel(
    const float* __restrict__ residual, const float* __restrict__ hstm,
    const float* __restrict__ hscm, const float* __restrict__ nw,
    const float* __restrict__ wavg, float* __restrict__ res1,
    __half* __restrict__ oh, __half* __restrict__ ol)
{
    const int bs = blockIdx.x, b = bs >> 10, s = bs & 1023, t = threadIdx.x;
    const size_t r4 = (size_t)bs * 256 + t;
    const size_t i0 = ((size_t)(b * 2 + 0) * 1024 + s) * 256 + t;
    const size_t i1 = ((size_t)(b * 2 + 1) * 1024 + s) * 256 + t;

    float4 r  = ((const float4*)residual)[r4];
    float4 c1 = ((const float4*)hscm)[i1];
    r.x += c1.x; r.y += c1.y; r.z += c1.z; r.w += c1.w;
    ((float4*)res1)[r4] = r;

    const float tot = block_sum256(r.x * r.x + r.y * r.y + r.z * r.z + r.w * r.w);
    const float scale = rsqrtf(tot * (1.f / (float)DM) + 1e-5f);

    float w0 = wavg[s], w1 = wavg[1024 + s], w2 = wavg[2048 + s], w3 = wavg[3072 + s];
    const float mx = fmaxf(fmaxf(w0, w1), fmaxf(w2, w3));
    w0 = __expf(w0 - mx); w1 = __expf(w1 - mx); w2 = __expf(w2 - mx); w3 = __expf(w3 - mx);
    const float inv = 1.f / (w0 + w1 + w2 + w3);
    w0 *= inv; w1 *= inv; w2 *= inv; w3 *= inv;

    const float4 a0 = ((const float4*)hstm)[i0];
    const float4 a1 = ((const float4*)hstm)[i1];
    const float4 c0 = ((const float4*)hscm)[i0];
    const float4 wn = ((const float4*)nw)[t];
    float o[4];
    o[0] = w0 * a0.x + w1 * a1.x + w2 * c0.x + w3 * (r.x * scale * wn.x);
    o[1] = w0 * a0.y + w1 * a1.y + w2 * c0.y + w3 * (r.y * scale * wn.y);
    o[2] = w0 * a0.z + w1 * a1.z + w2 * c0.z + w3 * (r.z * scale * wn.z);
    o[3] = w0 * a0.w + w1 * a1.w + w2 * c0.w + w3 * (r.w * scale * wn.w);
    const size_t e = r4 * 4;
#pragma unroll
    for (int k = 0; k < 4; k++) split1(o[k], oh + e + k, ol + e + k);
}

// res2 + rmsnorm + 5-way mix -> hmix fp32 (transposed next)
__global__ __launch_bounds__(256) void rms_mix_cm_kernel(
    const float* __restrict__ res1, const float* __restrict__ outm,
    const float* __restrict__ hstm, const float* __restrict__ hscm,
    const float* __restrict__ nw, const float* __restrict__ wavg,
    float* __restrict__ res2, float* __restrict__ hmix)
{
    const int bs = blockIdx.x, b = bs >> 10, s = bs & 1023, t = threadIdx.x;
    const size_t r4 = (size_t)bs * 256 + t;
    const size_t i0 = ((size_t)(b * 2 + 0) * 1024 + s) * 256 + t;
    const size_t i1 = ((size_t)(b * 2 + 1) * 1024 + s) * 256 + t;

    float4 r  = ((const float4*)res1)[r4];
    float4 om = ((const float4*)outm)[r4];
    r.x += om.x; r.y += om.y; r.z += om.z; r.w += om.w;
    ((float4*)res2)[r4] = r;

    const float tot = block_sum256(r.x * r.x + r.y * r.y + r.z * r.z + r.w * r.w);
    const float scale = rsqrtf(tot * (1.f / (float)DM) + 1e-5f);

    float w[5];
#pragma unroll
    for (int n = 0; n < 5; n++) w[n] = wavg[n * 1024 + s];
    float mx = w[0];
#pragma unroll
    for (int n = 1; n < 5; n++) mx = fmaxf(mx, w[n]);
    float sum = 0.f;
#pragma unroll
    for (int n = 0; n < 5; n++) { w[n] = __expf(w[n] - mx); sum += w[n]; }
    const float inv = 1.f / sum;
#pragma unroll
    for (int n = 0; n < 5; n++) w[n] *= inv;

    const float4 a0 = ((const float4*)hstm)[i0];
    const float4 a1 = ((const float4*)hstm)[i1];
    const float4 c0 = ((const float4*)hscm)[i0];
    const float4 c1 = ((const float4*)hscm)[i1];
    const float4 wn = ((const float4*)nw)[t];
    float4 o;
    o.x = w[0]*a0.x + w[1]*a1.x + w[2]*(r.x*scale*wn.x) + w[3]*c0.x + w[4]*c1.x;
    o.y = w[0]*a0.y + w[1]*a1.y + w[2]*(r.y*scale*wn.y) + w[3]*c0.y + w[4]*c1.y;
    o.z = w[0]*a0.z + w[1]*a1.z + w[2]*(r.z*scale*wn.z) + w[3]*c0.z + w[4]*c1.z;
    o.w = w[0]*a0.w + w[1]*a1.w + w[2]*(r.w*scale*wn.w) + w[3]*c0.w + w[4]*c1.w;
    ((float4*)hmix)[r4] = o;
}

// batched transpose fp32 -> fp16 hi/lo
__global__ __launch_bounds__(256) void transpose_h_kernel(
    const float* __restrict__ in, __half* __restrict__ oh, __half* __restrict__ ol)
{
    __shared__ float tile[32][33];
    const int b = blockIdx.z;
    const int r0 = blockIdx.y * 32, c0 = blockIdx.x * 32;
    const size_t base = (size_t)b * 1024 * 1024;
#pragma unroll
    for (int i = threadIdx.y; i < 32; i += 8)
        tile[i][threadIdx.x] = in[base + (size_t)(r0 + i) * 1024 + c0 + threadIdx.x];
    __syncthreads();
#pragma unroll
    for (int i = threadIdx.y; i < 32; i += 8) {
        const size_t o = base + (size_t)(c0 + i) * 1024 + r0 + threadIdx.x;
        split1(tile[threadIdx.x][i], oh + o, ol + o);
    }
}

// batched transpose fp32 -> fp32 (final output)
__global__ __launch_bounds__(256) void transpose_kernel(
    const float* __restrict__ in, float* __restrict__ out)
{
    __shared__ float tile[32][33];
    const int b = blockIdx.z;
    const int r0 = blockIdx.y * 32, c0 = blockIdx.x * 32;
    const size_t base = (size_t)b * 1024 * 1024;
#pragma unroll
    for (int i = threadIdx.y; i < 32; i += 8)
        tile[i][threadIdx.x] = in[base + (size_t)(r0 + i) * 1024 + c0 + threadIdx.x];
    __syncthreads();
#pragma unroll
    for (int i = threadIdx.y; i < 32; i += 8)
        out[base + (size_t)(c0 + i) * 1024 + r0 + threadIdx.x] = tile[threadIdx.x][i];
}

// ---------------------------------------------------------------------------
// host side
// ---------------------------------------------------------------------------
static const int SMEM256 = 3 * (2 * 128 * 80 + 2 * 256 * 80);   // 184320
static const int SMEM128 = 3 * (2 * 128 * 80 + 2 * 128 * 80);   // 122880

struct Bufs {
    float *xz, *xh, *dtb, *xdbl, *xpart, *res1, *hmix, *outm;
    __half *ah, *al, *bh, *bl, *dh, *dl;
};

static void split_w(const float* w, __half* hi, __half* lo, int n)
{
    split_w_kernel<<<(n + 255) / 256, 256>>>(w, hi, lo, n);
}

// input activation already in bufs.ah/al (lda=1024)
static void run_mamba(const Bufs& B, const float* const* P, float* out)
{
    const float* in_w   = P[0];
    const float* conv_w = P[1];
    const float* conv_b = P[2];
    const float* xproj  = P[3];
    const float* dt_w   = P[4];
    const float* dt_b   = P[5];
    const float* A_log  = P[6];
    const float* Dp     = P[7];
    const float* out_w  = P[8];

    // in_proj
    split_w(in_w, B.bh, B.bl, 2 * DI_ * DM);
    gemm_cp<256, 0><<<dim3(2 * DI_ / 256, ROWS / 128, 1), 256, SMEM256>>>(
        B.ah, B.al, DM, B.bh, B.bl, nullptr, B.xz, ROWS, 2 * DI_, DM, DM);

    // conv + silu (emits xh fp32 + hi/lo)
    conv_silu_kernel<<<(ROWS * DI_) / 256, 256>>>(B.xz, conv_w, conv_b, B.xh, B.ah, B.al);

    // x_proj: split-K=4 partials, then reduce (emits xdbl fp32 + dt-slice hi/lo)
    split_w(xproj, B.bh, B.bl, XD * DI_);
    gemm_cp<128, 0><<<dim3(1, ROWS / 128, KSP), 256, SMEM128>>>(
        B.ah, B.al, DI_, B.bh, B.bl, nullptr, B.xpart, ROWS, XD, DI_, DI_ / KSP);
    reduce_xproj_kernel<<<(ROWS * XD) / 256, 256>>>(B.xpart, B.xdbl, B.dh, B.dl);

    // dt_proj (+softplus)
    split_w(dt_w, B.bh, B.bl, DI_ * DTR);
    gemm_cp<256, 1><<<dim3(DI_ / 256, ROWS / 128, 1), 256, SMEM256>>>(
        B.dh, B.dl, DTR, B.bh, B.bl, dt_b, B.dtb, ROWS, DI_, DTR, DTR);

    // scan (emits y hi/lo into ah/al)
    scan_kernel<<<dim3(DI_ / 128, BSZ), 128>>>(B.dtb, B.xh, B.xdbl, B.xz, A_log, Dp,
                                               B.ah, B.al);

    // out_proj
    split_w(out_w, B.bh, B.bl, DM * DI_);
    gemm_cp<256, 0><<<dim3(DM / 256, ROWS / 128, 1), 256, SMEM256>>>(
        B.ah, B.al, DI_, B.bh, B.bl, nullptr, out, ROWS, DM, DI_, DI_);
}

extern "C" void kernel_launch(void* const* d_in, const int* in_sizes, int n_in,
                              void* d_out, int out_size)
{
    cudaFuncSetAttribute(gemm_cp<256, 0>, cudaFuncAttributeMaxDynamicSharedMemorySize, SMEM256);
    cudaFuncSetAttribute(gemm_cp<256, 1>, cudaFuncAttributeMaxDynamicSharedMemorySize, SMEM256);
    cudaFuncSetAttribute(gemm_cp<128, 0>, cudaFuncAttributeMaxDynamicSharedMemorySize, SMEM128);

    const float* hstm     = (const float*)d_in[0];
    const float* hscm     = (const float*)d_in[1];
    const float* residual = (const float*)d_in[2];
    const float* norm_tm  = (const float*)d_in[3];
    const float* wavg_tm  = (const float*)d_in[4];

    const float *norm_cm, *wavg_cm;
    int btm;
    const int bcm = 16;
    if (in_sizes[5] == 1024) {            // dict order
        norm_cm = (const float*)d_in[5];
        wavg_cm = (const float*)d_in[6];
        btm = 7;
    } else {                              // signature order
        btm = 5;
        norm_cm = (const float*)d_in[14];
        wavg_cm = (const float*)d_in[15];
    }
    const float* P_tm[9];
    const float* P_cm[9];
    for (int i = 0; i < 9; i++) {
        P_tm[i] = (const float*)d_in[btm + i];
        P_cm[i] = (const float*)d_in[bcm + i];
    }

    Bufs B;
    cudaGetSymbolAddress((void**)&B.xz,    g_xz);
    cudaGetSymbolAddress((void**)&B.xh,    g_xh);
    cudaGetSymbolAddress((void**)&B.dtb,   g_dt);
    cudaGetSymbolAddress((void**)&B.xdbl,  g_xdbl);
    cudaGetSymbolAddress((void**)&B.xpart, g_xpart);
    cudaGetSymbolAddress((void**)&B.res1,  g_res1);
    cudaGetSymbolAddress((void**)&B.hmix,  g_hmix);
    cudaGetSymbolAddress((void**)&B.outm,  g_outm);
    cudaGetSymbolAddress((void**)&B.ah,    g_ah);
    cudaGetSymbolAddress((void**)&B.al,    g_al);
    cudaGetSymbolAddress((void**)&B.bh,    g_bh);
    cudaGetSymbolAddress((void**)&B.bl,    g_bl);
    cudaGetSymbolAddress((void**)&B.dh,    g_dh);
    cudaGetSymbolAddress((void**)&B.dl,    g_dl);

    float* dout = (float*)d_out;
    const long total = (long)BSZ * SEQ * DM;
    float* res2_out = (out_size >= 2 * total) ? (dout + total) : B.res1;

    // --- token-mixer path ---
    rms_mix_tm_kernel<<<ROWS, 256>>>(residual, hstm, hscm, norm_tm, wavg_tm,
                                     B.res1, B.ah, B.al);
    run_mamba(B, P_tm, B.outm);

    // --- channel-mixer path ---
    rms_mix_cm_kernel<<<ROWS, 256>>>(B.res1, B.outm, hstm, hscm, norm_cm, wavg_cm,
                                     res2_out, B.hmix);
    transpose_h_kernel<<<dim3(32, 32, BSZ), dim3(32, 8)>>>(B.hmix, B.ah, B.al);
    run_mamba(B, P_cm, B.outm);
    transpose_kernel<<<dim3(32, 32, BSZ), dim3(32, 8)>>>(B.outm, dout);
}

// round 5
// speedup vs baseline: 1.0130x; 1.0130x over previous
#include <cuda_runtime.h>
#include <cuda_fp16.h>
#include <cstdint>
#include <math.h>

// ---------------------------------------------------------------------------
// SambaMixerBlock: B=8, S=D=1024, N=16, DCONV=4, EXPAND=2 -> DI=2048, DT_RANK=64
// Round 5: ldmatrix fragment loads in the HMMA GEMM (was scalar LDS-bound).
// ---------------------------------------------------------------------------

#define BSZ   8
#define SEQ   1024
#define DM    1024
#define DI_   2048
#define NST   16
#define DTR   64
#define XD    96
#define ROWS  (BSZ*SEQ)
#define KSP   4                      // x_proj split-K factor

// fp32 scratch
__device__ float g_xz  [(size_t)ROWS * 2 * DI_];
__device__ float g_xh  [(size_t)ROWS * DI_];
__device__ float g_dt  [(size_t)ROWS * DI_];
__device__ float g_xdbl[(size_t)ROWS * XD];
__device__ float g_xpart[(size_t)KSP * ROWS * XD];
__device__ float g_res1[(size_t)ROWS * DM];
__device__ float g_hmix[(size_t)ROWS * DM];
__device__ float g_outm[(size_t)ROWS * DM];
// fp16 hi/lo operand scratch
__device__ __half g_ah[(size_t)ROWS * DI_];
__device__ __half g_al[(size_t)ROWS * DI_];
__device__ __half g_bh[(size_t)2 * DI_ * DM];
__device__ __half g_bl[(size_t)2 * DI_ * DM];
__device__ __half g_dh[(size_t)ROWS * DTR];
__device__ __half g_dl[(size_t)ROWS * DTR];

// ---------------------------------------------------------------------------
__device__ __forceinline__ void split1(float v, __half* hi, __half* lo)
{
    __half h = __float2half_rn(v);
    *hi = h;
    *lo = __float2half_rn(v - __half2float(h));
}

__device__ __forceinline__ void cpa16(uint32_t d, const void* s)
{
    asm volatile("cp.async.cg.shared.global [%0], [%1], 16;" :: "r"(d), "l"(s));
}
__device__ __forceinline__ void cpa16z(uint32_t d, const void* s, bool ok)
{
    int sz = ok ? 16 : 0;
    asm volatile("cp.async.cg.shared.global [%0], [%1], 16, %2;"
                 :: "r"(d), "l"(s), "r"(sz));
}
#define CP_COMMIT() asm volatile("cp.async.commit_group;" ::: "memory")
#define CP_WAIT1()  asm volatile("cp.async.wait_group 1;" ::: "memory")

__device__ __forceinline__ void mma16816(float* d, const uint32_t* a, const uint32_t* b)
{
    asm volatile(
        "mma.sync.aligned.m16n8k16.row.col.f32.f16.f16.f32 "
        "{%0,%1,%2,%3}, {%4,%5,%6,%7}, {%8,%9}, {%0,%1,%2,%3};"
        : "+f"(d[0]), "+f"(d[1]), "+f"(d[2]), "+f"(d[3])
        : "r"(a[0]), "r"(a[1]), "r"(a[2]), "r"(a[3]), "r"(b[0]), "r"(b[1]));
}

__device__ __forceinline__ void ldmx4(uint32_t* r, uint32_t addr)
{
    asm volatile("ldmatrix.sync.aligned.m8n8.x4.shared.b16 {%0,%1,%2,%3}, [%4];"
                 : "=r"(r[0]), "=r"(r[1]), "=r"(r[2]), "=r"(r[3]) : "r"(addr));
}

// ---------------------------------------------------------------------------
// Pipelined HMMA GEMM: C = A(M,K) * B(N,K)^T, fp16 hi/lo x3, fp32 acc.
// CTA 128 x TN, BK=32, 3-stage cp.async, ldmatrix fragment loads.
// smem row stride 80B -> conflict-free (LDS and ldmatrix phases).
// EPI==1: C = softplus(C + bias)
// ---------------------------------------------------------------------------
template<int TN, int EPI>
__global__ __launch_bounds__(256, 1) void gemm_cp(
    const __half* __restrict__ Ah, const __half* __restrict__ Al, int lda,
    const __half* __restrict__ Bh, const __half* __restrict__ Bl,
    const float* __restrict__ bias, float* __restrict__ Cbase,
    int M, int Nsz, int Kfull, int Ksub)
{
    constexpr int ABY = 128 * 80;
    constexpr int BBY = TN * 80;
    constexpr int STG = 2 * ABY + 2 * BBY;
    constexpr int JN  = TN / 32;

    extern __shared__ __align__(16) char smem[];
    const uint32_t sb0 = (uint32_t)__cvta_generic_to_shared(smem);

    const int tid = threadIdx.x, wid = tid >> 5, lid = tid & 31;
    const int bm = blockIdx.y * 128, bn = blockIdx.x * TN;
    const int koff = blockIdx.z * Ksub;
    float* C = Cbase + (size_t)blockIdx.z * M * Nsz;
    const int wm = (wid & 1) * 64, wn = (wid >> 1) * (TN / 4);
    const int g = lid >> 2, t4 = lid & 3;
    const int S = Ksub >> 5;

    // ldmatrix lane-address components
    const int lr = lid & 7, tq = lid >> 3;
    const int a_ro = (tq & 1) * 8, a_co = (tq >> 1) * 16;   // A: tiles 1,3 -> +8 rows; 2,3 -> +16B
    const int b_ro = (tq >> 1) * 8, b_co = (tq & 1) * 16;   // B: tiles 2,3 -> next j; 1,3 -> k-half

    auto issue = [&](int s) {
        const int k0 = koff + (s << 5);
        const uint32_t st = sb0 + (s % 3) * STG;
#pragma unroll
        for (int i = 0; i < 2; i++) {
            const int id = tid + i * 256, row = id >> 2, q = id & 3;
            const size_t go = (size_t)(bm + row) * lda + k0 + q * 8;
            cpa16(st + row * 80 + q * 16, Ah + go);
            cpa16(st + ABY + row * 80 + q * 16, Al + go);
        }
#pragma unroll
        for (int i = 0; i < TN / 64; i++) {
            const int id = tid + i * 256, row = id >> 2, q = id & 3;
            const bool ok = (bn + row) < Nsz;
            const int r2 = ok ? (bn + row) : 0;
            const size_t go = (size_t)r2 * Kfull + k0 + q * 8;
            cpa16z(st + 2 * ABY + row * 80 + q * 16, Bh + go, ok);
            cpa16z(st + 2 * ABY + BBY + row * 80 + q * 16, Bl + go, ok);
        }
    };

    float acc[4][JN][4];
#pragma unroll
    for (int i = 0; i < 4; i++)
#pragma unroll
        for (int j = 0; j < JN; j++)
#pragma unroll
            for (int c = 0; c < 4; c++) acc[i][j][c] = 0.f;

    issue(0); CP_COMMIT();
    if (S > 1) issue(1);
    CP_COMMIT();

    for (int s = 0; s < S; s++) {
        CP_WAIT1();
        __syncthreads();
        if (s + 2 < S) issue(s + 2);
        CP_COMMIT();

        const uint32_t st = sb0 + (s % 3) * STG;
#pragma unroll
        for (int kk = 0; kk < 2; kk++) {
            const int cb = kk * 32;
            uint32_t ah[4][4], al[4][4];
#pragma unroll
            for (int i = 0; i < 4; i++) {
                const uint32_t aaddr = st + (wm + i * 16 + a_ro + lr) * 80 + cb + a_co;
                ldmx4(ah[i], aaddr);
                ldmx4(al[i], aaddr + ABY);
            }
#pragma unroll
            for (int j2 = 0; j2 < JN / 2; j2++) {
                const uint32_t baddr = st + 2 * ABY
                    + (wn + j2 * 16 + b_ro + lr) * 80 + cb + b_co;
                uint32_t bh[4], bl[4];
                ldmx4(bh, baddr);          // bh[0..1]=j even, bh[2..3]=j odd
                ldmx4(bl, baddr + BBY);
#pragma unroll
                for (int i = 0; i < 4; i++) {
                    mma16816(acc[i][2 * j2],     ah[i], bh);
                    mma16816(acc[i][2 * j2 + 1], ah[i], bh + 2);
                }
#pragma unroll
                for (int i = 0; i < 4; i++) {
                    mma16816(acc[i][2 * j2],     al[i], bh);
                    mma16816(acc[i][2 * j2 + 1], al[i], bh + 2);
                }
#pragma unroll
                for (int i = 0; i < 4; i++) {
                    mma16816(acc[i][2 * j2],     ah[i], bl);
                    mma16816(acc[i][2 * j2 + 1], ah[i], bl + 2);
                }
            }
        }
    }

#pragma unroll
    for (int i = 0; i < 4; i++) {
        const int r0 = bm + wm + i * 16 + g;
#pragma unroll
        for (int j = 0; j < JN; j++) {
            const int c = bn + wn + j * 8 + t4 * 2;
            if (c < Nsz) {
                float v0 = acc[i][j][0], v1 = acc[i][j][1];
                float v2 = acc[i][j][2], v3 = acc[i][j][3];
                if (EPI == 1) {
                    const float b0 = bias[c], b1 = bias[c + 1];
                    v0 += b0; v1 += b1; v2 += b0; v3 += b1;
                    v0 = (v0 > 20.f) ? v0 : log1pf(__expf(v0));
                    v1 = (v1 > 20.f) ? v1 : log1pf(__expf(v1));
                    v2 = (v2 > 20.f) ? v2 : log1pf(__expf(v2));
                    v3 = (v3 > 20.f) ? v3 : log1pf(__expf(v3));
                }
                *(float2*)(C + (size_t)r0 * Nsz + c)       = make_float2(v0, v1);
                *(float2*)(C + (size_t)(r0 + 8) * Nsz + c) = make_float2(v2, v3);
            }
        }
    }
}

// ---------------------------------------------------------------------------
__global__ __launch_bounds__(256) void split_w_kernel(
    const float* __restrict__ w, __half* __restrict__ hi, __half* __restrict__ lo, int n)
{
    const int i = blockIdx.x * 256 + threadIdx.x;
    if (i < n) split1(w[i], hi + i, lo + i);
}

__global__ __launch_bounds__(256) void reduce_xproj_kernel(
    const float* __restrict__ part, float* __restrict__ xdbl,
    __half* __restrict__ dh, __half* __restrict__ dl)
{
    const size_t n1 = (size_t)ROWS * XD;
    const size_t i = (size_t)blockIdx.x * 256 + threadIdx.x;
    float s = part[i] + part[i + n1] + part[i + 2 * n1] + part[i + 3 * n1];
    xdbl[i] = s;
    const int col = (int)(i % XD);
    if (col < DTR) {
        const size_t row = i / XD;
        split1(s, dh + row * DTR + col, dl + row * DTR + col);
    }
}

// ---------------------------------------------------------------------------
__global__ __launch_bounds__(256) void conv_silu_kernel(
    const float* __restrict__ xz, const float* __restrict__ w,
    const float* __restrict__ bias, float* __restrict__ xh,
    __half* __restrict__ oh, __half* __restrict__ ol)
{
    const long i = (long)blockIdx.x * 256 + threadIdx.x;
    const int  d = (int)(i & (DI_ - 1));
    const long bl = i >> 11;
    const int  l = (int)(bl & (SEQ - 1));
    const long b = bl >> 10;

    const float* base = xz + ((size_t)b * SEQ) * (2 * DI_) + d;
    float acc = bias[d];
    const float w0 = w[d * 4 + 0], w1 = w[d * 4 + 1], w2 = w[d * 4 + 2], w3 = w[d * 4 + 3];
    if (l >= 3) acc += w0 * base[(size_t)(l - 3) * (2 * DI_)];
    if (l >= 2) acc += w1 * base[(size_t)(l - 2) * (2 * DI_)];
    if (l >= 1) acc += w2 * base[(size_t)(l - 1) * (2 * DI_)];
    acc += w3 * base[(size_t)l * (2 * DI_)];
    acc = acc / (1.f + __expf(-acc));
    xh[i] = acc;
    split1(acc, oh + i, ol + i);
}

// ---------------------------------------------------------------------------
__global__ __launch_bounds__(128) void scan_kernel(
    const float* __restrict__ dtb, const float* __restrict__ xh,
    const float* __restrict__ xdbl, const float* __restrict__ xz,
    const float* __restrict__ A_log, const float* __restrict__ Dp,
    __half* __restrict__ yh, __half* __restrict__ yl)
{
    const int b = blockIdx.y;
    const int d = blockIdx.x * 128 + threadIdx.x;
    const int tid = threadIdx.x;

    float A[NST], h[NST];
#pragma unroll
    for (int n = 0; n < NST; n++) {
        A[n] = -__expf(A_log[d * NST + n]);
        h[n] = 0.f;
    }
    const float dval = Dp[d];

    __shared__ float sB[2][NST], sC[2][NST];
    const size_t rowbase = (size_t)b * SEQ;

    if (tid < 2 * NST) {
        for (int p = 0; p < 2; p++) {
            float v = xdbl[(rowbase + p) * XD + DTR + tid];
            if (tid < NST) sB[p][tid] = v; else sC[p][tid - NST] = v;
        }
    }
    float bc_next = 0.f;
    if (tid < 2 * NST) bc_next = xdbl[(rowbase + 2) * XD + DTR + tid];

    float dq[2], xq[2], zq[2];
#pragma unroll
    for (int p = 0; p < 2; p++) {
        const size_t idx = (rowbase + p) * DI_ + d;
        dq[p] = dtb[idx];
        xq[p] = xh[idx];
        zq[p] = xz[(rowbase + p) * (2 * DI_) + DI_ + d];
    }
    __syncthreads();

    for (int l = 0; l < SEQ; l++) {
        const int par = l & 1;
        const float dtv = dq[par], xv = xq[par], zv = zq[par];

        const int lp = (l + 2 < SEQ) ? l + 2 : SEQ - 1;
        const size_t idx2 = (rowbase + lp) * DI_ + d;
        dq[par] = dtb[idx2];
        xq[par] = xh[idx2];
        zq[par] = xz[(rowbase + lp) * (2 * DI_) + DI_ + d];

        const float dx = dtv * xv;
        float acc = 0.f;
#pragma unroll
        for (int n = 0; n < NST; n++) {
            h[n] = __expf(dtv * A[n]) * h[n] + dx * sB[par][n];
            acc += h[n] * sC[par][n];
        }
        acc += xv * dval;
        acc *= zv / (1.f + __expf(-zv));

        const size_t oidx = (rowbase + l) * DI_ + d;
        split1(acc, yh + oidx, yl + oidx);

        __syncthreads();
        if (tid < 2 * NST) {
            if (tid < NST) sB[par][tid] = bc_next; else sC[par][tid - NST] = bc_next;
            const int lq = (l + 3 < SEQ) ? l + 3 : SEQ - 1;
            bc_next = xdbl[(rowbase + lq) * XD + DTR + tid];
        }
    }
}

// ---------------------------------------------------------------------------
__device__ __forceinline__ float block_sum256(float v)
{
    __shared__ float red[8];
    const int lane = threadIdx.x & 31, w = threadIdx.x >> 5;
#pragma unroll
    for (int o = 16; o; o >>= 1) v += __shfl_xor_sync(0xffffffffu, v, o);
    if (!lane) red[w] = v;
    __syncthreads();
    if (w == 0) {
        v = (lane < 8) ? red[lane] : 0.f;
#pragma unroll
        for (int o = 4; o; o >>= 1) v += __shfl_xor_sync(0xffffffffu, v, o);
        if (!lane) red[0] = v;
    }
    __syncthreads();
    return red[0];
}

__global__ __launch_bounds__(256) void rms_mix_tm_kernel(
    const float* __restrict__ residual, const float* __restrict__ hstm,
    const float* __restrict__ hscm, const float* __restrict__ nw,
    const float* __restrict__ wavg, float* __restrict__ res1,
    __half* __restrict__ oh, __half* __restrict__ ol)
{
    const int bs = blockIdx.x, b = bs >> 10, s = bs & 1023, t = threadIdx.x;
    const size_t r4 = (size_t)bs * 256 + t;
    const size_t i0 = ((size_t)(b * 2 + 0) * 1024 + s) * 256 + t;
    const size_t i1 = ((size_t)(b * 2 + 1) * 1024 + s) * 256 + t;

    float4 r  = ((const float4*)residual)[r4];
    float4 c1 = ((const float4*)hscm)[i1];
    r.x += c1.x; r.y += c1.y; r.z += c1.z; r.w += c1.w;
    ((float4*)res1)[r4] = r;

    const float tot = block_sum256(r.x * r.x + r.y * r.y + r.z * r.z + r.w * r.w);
    const float scale = rsqrtf(tot * (1.f / (float)DM) + 1e-5f);

    float w0 = wavg[s], w1 = wavg[1024 + s], w2 = wavg[2048 + s], w3 = wavg[3072 + s];
    const float mx = fmaxf(fmaxf(w0, w1), fmaxf(w2, w3));
    w0 = __expf(w0 - mx); w1 = __expf(w1 - mx); w2 = __expf(w2 - mx); w3 = __expf(w3 - mx);
    const float inv = 1.f / (w0 + w1 + w2 + w3);
    w0 *= inv; w1 *= inv; w2 *= inv; w3 *= inv;

    const float4 a0 = ((const float4*)hstm)[i0];
    const float4 a1 = ((const float4*)hstm)[i1];
    const float4 c0 = ((const float4*)hscm)[i0];
    const float4 wn = ((const float4*)nw)[t];
    float o[4];
    o[0] = w0 * a0.x + w1 * a1.x + w2 * c0.x + w3 * (r.x * scale * wn.x);
    o[1] = w0 * a0.y + w1 * a1.y + w2 * c0.y + w3 * (r.y * scale * wn.y);
    o[2] = w0 * a0.z + w1 * a1.z + w2 * c0.z + w3 * (r.z * scale * wn.z);
    o[3] = w0 * a0.w + w1 * a1.w + w2 * c0.w + w3 * (r.w * scale * wn.w);
    const size_t e = r4 * 4;
#pragma unroll
    for (int k = 0; k < 4; k++) split1(o[k], oh + e + k, ol + e + k);
}

__global__ __launch_bounds__(256) void rms_mix_cm_kernel(
    const float* __restrict__ res1, const float* __restrict__ outm,
    const float* __restrict__ hstm, const float* __restrict__ hscm,
    const float* __restrict__ nw, const float* __restrict__ wavg,
    float* __restrict__ res2, float* __restrict__ hmix)
{
    const int bs = blockIdx.x, b = bs >> 10, s = bs & 1023, t = threadIdx.x;
    const size_t r4 = (size_t)bs * 256 + t;
    const size_t i0 = ((size_t)(b * 2 + 0) * 1024 + s) * 256 + t;
    const size_t i1 = ((size_t)(b * 2 + 1) * 1024 + s) * 256 + t;

    float4 r  = ((const float4*)res1)[r4];
    float4 om = ((const float4*)outm)[r4];
    r.x += om.x; r.y += om.y; r.z += om.z; r.w += om.w;
    ((float4*)res2)[r4] = r;

    const float tot = block_sum256(r.x * r.x + r.y * r.y + r.z * r.z + r.w * r.w);
    const float scale = rsqrtf(tot * (1.f / (float)DM) + 1e-5f);

    float w[5];
#pragma unroll
    for (int n = 0; n < 5; n++) w[n] = wavg[n * 1024 + s];
    float mx = w[0];
#pragma unroll
    for (int n = 1; n < 5; n++) mx = fmaxf(mx, w[n]);
    float sum = 0.f;
#pragma unroll
    for (int n = 0; n < 5; n++) { w[n] = __expf(w[n] - mx); sum += w[n]; }
    const float inv = 1.f / sum;
#pragma unroll
    for (int n = 0; n < 5; n++) w[n] *= inv;

    const float4 a0 = ((const float4*)hstm)[i0];
    const float4 a1 = ((const float4*)hstm)[i1];
    const float4 c0 = ((const float4*)hscm)[i0];
    const float4 c1 = ((const float4*)hscm)[i1];
    const float4 wn = ((const float4*)nw)[t];
    float4 o;
    o.x = w[0]*a0.x + w[1]*a1.x + w[2]*(r.x*scale*wn.x) + w[3]*c0.x + w[4]*c1.x;
    o.y = w[0]*a0.y + w[1]*a1.y + w[2]*(r.y*scale*wn.y) + w[3]*c0.y + w[4]*c1.y;
    o.z = w[0]*a0.z + w[1]*a1.z + w[2]*(r.z*scale*wn.z) + w[3]*c0.z + w[4]*c1.z;
    o.w = w[0]*a0.w + w[1]*a1.w + w[2]*(r.w*scale*wn.w) + w[3]*c0.w + w[4]*c1.w;
    ((float4*)hmix)[r4] = o;
}

__global__ __launch_bounds__(256) void transpose_h_kernel(
    const float* __restrict__ in, __half* __restrict__ oh, __half* __restrict__ ol)
{
    __shared__ float tile[32][33];
    const int b = blockIdx.z;
    const int r0 = blockIdx.y * 32, c0 = blockIdx.x * 32;
    const size_t base = (size_t)b * 1024 * 1024;
#pragma unroll
    for (int i = threadIdx.y; i < 32; i += 8)
        tile[i][threadIdx.x] = in[base + (size_t)(r0 + i) * 1024 + c0 + threadIdx.x];
    __syncthreads();
#pragma unroll
    for (int i = threadIdx.y; i < 32; i += 8) {
        const size_t o = base + (size_t)(c0 + i) * 1024 + r0 + threadIdx.x;
        split1(tile[threadIdx.x][i], oh + o, ol + o);
    }
}

__global__ __launch_bounds__(256) void transpose_kernel(
    const float* __restrict__ in, float* __restrict__ out)
{
    __shared__ float tile[32][33];
    const int b = blockIdx.z;
    const int r0 = blockIdx.y * 32, c0 = blockIdx.x * 32;
    const size_t base = (size_t)b * 1024 * 1024;
#pragma unroll
    for (int i = threadIdx.y; i < 32; i += 8)
        tile[i][threadIdx.x] = in[base + (size_t)(r0 + i) * 1024 + c0 + threadIdx.x];
    __syncthreads();
#pragma unroll
    for (int i = threadIdx.y; i < 32; i += 8)
        out[base + (size_t)(c0 + i) * 1024 + r0 + threadIdx.x] = tile[threadIdx.x][i];
}

// ---------------------------------------------------------------------------
// host side
// ---------------------------------------------------------------------------
static const int SMEM256 = 3 * (2 * 128 * 80 + 2 * 256 * 80);   // 184320
static const int SMEM128 = 3 * (2 * 128 * 80 + 2 * 128 * 80);   // 122880

struct Bufs {
    float *xz, *xh, *dtb, *xdbl, *xpart, *res1, *hmix, *outm;
    __half *ah, *al, *bh, *bl, *dh, *dl;
};

static void split_w(const float* w, __half* hi, __half* lo, int n)
{
    split_w_kernel<<<(n + 255) / 256, 256>>>(w, hi, lo, n);
}

static void run_mamba(const Bufs& B, const float* const* P, float* out)
{
    const float* in_w   = P[0];
    const float* conv_w = P[1];
    const float* conv_b = P[2];
    const float* xproj  = P[3];
    const float* dt_w   = P[4];
    const float* dt_b   = P[5];
    const float* A_log  = P[6];
    const float* Dp     = P[7];
    const float* out_w  = P[8];

    split_w(in_w, B.bh, B.bl, 2 * DI_ * DM);
    gemm_cp<256, 0><<<dim3(2 * DI_ / 256, ROWS / 128, 1), 256, SMEM256>>>(
        B.ah, B.al, DM, B.bh, B.bl, nullptr, B.xz, ROWS, 2 * DI_, DM, DM);

    conv_silu_kernel<<<(ROWS * DI_) / 256, 256>>>(B.xz, conv_w, conv_b, B.xh, B.ah, B.al);

    split_w(xproj, B.bh, B.bl, XD * DI_);
    gemm_cp<128, 0><<<dim3(1, ROWS / 128, KSP), 256, SMEM128>>>(
        B.ah, B.al, DI_, B.bh, B.bl, nullptr, B.xpart, ROWS, XD, DI_, DI_ / KSP);
    reduce_xproj_kernel<<<(ROWS * XD) / 256, 256>>>(B.xpart, B.xdbl, B.dh, B.dl);

    split_w(dt_w, B.bh, B.bl, DI_ * DTR);
    gemm_cp<256, 1><<<dim3(DI_ / 256, ROWS / 128, 1), 256, SMEM256>>>(
        B.dh, B.dl, DTR, B.bh, B.bl, dt_b, B.dtb, ROWS, DI_, DTR, DTR);

    scan_kernel<<<dim3(DI_ / 128, BSZ), 128>>>(B.dtb, B.xh, B.xdbl, B.xz, A_log, Dp,
                                               B.ah, B.al);

    split_w(out_w, B.bh, B.bl, DM * DI_);
    gemm_cp<256, 0><<<dim3(DM / 256, ROWS / 128, 1), 256, SMEM256>>>(
        B.ah, B.al, DI_, B.bh, B.bl, nullptr, out, ROWS, DM, DI_, DI_);
}

extern "C" void kernel_launch(void* const* d_in, const int* in_sizes, int n_in,
                              void* d_out, int out_size)
{
    cudaFuncSetAttribute(gemm_cp<256, 0>, cudaFuncAttributeMaxDynamicSharedMemorySize, SMEM256);
    cudaFuncSetAttribute(gemm_cp<256, 1>, cudaFuncAttributeMaxDynamicSharedMemorySize, SMEM256);
    cudaFuncSetAttribute(gemm_cp<128, 0>, cudaFuncAttributeMaxDynamicSharedMemorySize, SMEM128);

    const float* hstm     = (const float*)d_in[0];
    const float* hscm     = (const float*)d_in[1];
    const float* residual = (const float*)d_in[2];
    const float* norm_tm  = (const float*)d_in[3];
    const float* wavg_tm  = (const float*)d_in[4];

    const float *norm_cm, *wavg_cm;
    int btm;
    const int bcm = 16;
    if (in_sizes[5] == 1024) {            // dict order
        norm_cm = (const float*)d_in[5];
        wavg_cm = (const float*)d_in[6];
        btm = 7;
    } else {                              // signature order
        btm = 5;
        norm_cm = (const float*)d_in[14];
        wavg_cm = (const float*)d_in[15];
    }
    const float* P_tm[9];
    const float* P_cm[9];
    for (int i = 0; i < 9; i++) {
        P_tm[i] = (const float*)d_in[btm + i];
        P_cm[i] = (const float*)d_in[bcm + i];
    }

    Bufs B;
    cudaGetSymbolAddress((void**)&B.xz,    g_xz);
    cudaGetSymbolAddress((void**)&B.xh,    g_xh);
    cudaGetSymbolAddress((void**)&B.dtb,   g_dt);
    cudaGetSymbolAddress((void**)&B.xdbl,  g_xdbl);
    cudaGetSymbolAddress((void**)&B.xpart, g_xpart);
    cudaGetSymbolAddress((void**)&B.res1,  g_res1);
    cudaGetSymbolAddress((void**)&B.hmix,  g_hmix);
    cudaGetSymbolAddress((void**)&B.outm,  g_outm);
    cudaGetSymbolAddress((void**)&B.ah,    g_ah);
    cudaGetSymbolAddress((void**)&B.al,    g_al);
    cudaGetSymbolAddress((void**)&B.bh,    g_bh);
    cudaGetSymbolAddress((void**)&B.bl,    g_bl);
    cudaGetSymbolAddress((void**)&B.dh,    g_dh);
    cudaGetSymbolAddress((void**)&B.dl,    g_dl);

    float* dout = (float*)d_out;
    const long total = (long)BSZ * SEQ * DM;
    float* res2_out = (out_size >= 2 * total) ? (dout + total) : B.res1;

    // --- token-mixer path ---
    rms_mix_tm_kernel<<<ROWS, 256>>>(residual, hstm, hscm, norm_tm, wavg_tm,
                                     B.res1, B.ah, B.al);
    run_mamba(B, P_tm, B.outm);

    // --- channel-mixer path ---
    rms_mix_cm_kernel<<<ROWS, 256>>>(B.res1, B.outm, hstm, hscm, norm_cm, wavg_cm,
                                     res2_out, B.hmix);
    transpose_h_kernel<<<dim3(32, 32, BSZ), dim3(32, 8)>>>(B.hmix, B.ah, B.al);
    run_mamba(B, P_cm, B.outm);
    transpose_kernel<<<dim3(32, 32, BSZ), dim3(32, 8)>>>(B.outm, dout);
}

// round 6
// speedup vs baseline: 1.5384x; 1.5187x over previous
#include <cuda_runtime.h>
#include <cuda_fp16.h>
#include <cstdint>
#include <math.h>

// ---------------------------------------------------------------------------
// SambaMixerBlock: B=8, S=D=1024, N=16, DCONV=4, EXPAND=2 -> DI=2048, DT_RANK=64
// Round 6: single-fp16 HMMA (1 MMA/tile, was 3 with hi/lo split) + fp16
//          intermediates. Legacy mma.sync pipe was saturated; cut its work 3x.
// ---------------------------------------------------------------------------

#define BSZ   8
#define SEQ   1024
#define DM    1024
#define DI_   2048
#define NST   16
#define DTR   64
#define XD    96
#define ROWS  (BSZ*SEQ)
#define KSP   4                      // x_proj split-K factor

// fp32 scratch
__device__ float g_dt  [(size_t)ROWS * DI_];
__device__ float g_xdbl[(size_t)ROWS * XD];
__device__ float g_xpart[(size_t)KSP * ROWS * XD];
__device__ float g_res1[(size_t)ROWS * DM];
__device__ float g_hmix[(size_t)ROWS * DM];
__device__ float g_outm[(size_t)ROWS * DM];
// fp16 scratch
__device__ __half g_xzh [(size_t)ROWS * 2 * DI_];   // in_proj out (x|z)
__device__ __half g_xh16[(size_t)ROWS * DI_];       // conv out
__device__ __half g_y16 [(size_t)ROWS * DI_];       // scan out
__device__ __half g_dth [(size_t)ROWS * DTR];       // dt-rank slice
__device__ __half g_mix16[(size_t)ROWS * DM];       // mixed input (A of in_proj)
__device__ __half g_wh  [(size_t)2 * DI_ * DM];     // converted weights

// ---------------------------------------------------------------------------
__device__ __forceinline__ void cpa16(uint32_t d, const void* s)
{
    asm volatile("cp.async.cg.shared.global [%0], [%1], 16;" :: "r"(d), "l"(s));
}
__device__ __forceinline__ void cpa16z(uint32_t d, const void* s, bool ok)
{
    int sz = ok ? 16 : 0;
    asm volatile("cp.async.cg.shared.global [%0], [%1], 16, %2;"
                 :: "r"(d), "l"(s), "r"(sz));
}
#define CP_COMMIT() asm volatile("cp.async.commit_group;" ::: "memory")
#define CP_WAIT1()  asm volatile("cp.async.wait_group 1;" ::: "memory")

__device__ __forceinline__ void mma16816(float* d, const uint32_t* a, const uint32_t* b)
{
    asm volatile(
        "mma.sync.aligned.m16n8k16.row.col.f32.f16.f16.f32 "
        "{%0,%1,%2,%3}, {%4,%5,%6,%7}, {%8,%9}, {%0,%1,%2,%3};"
        : "+f"(d[0]), "+f"(d[1]), "+f"(d[2]), "+f"(d[3])
        : "r"(a[0]), "r"(a[1]), "r"(a[2]), "r"(a[3]), "r"(b[0]), "r"(b[1]));
}

__device__ __forceinline__ void ldmx4(uint32_t* r, uint32_t addr)
{
    asm volatile("ldmatrix.sync.aligned.m8n8.x4.shared.b16 {%0,%1,%2,%3}, [%4];"
                 : "=r"(r[0]), "=r"(r[1]), "=r"(r[2]), "=r"(r[3]) : "r"(addr));
}

// ---------------------------------------------------------------------------
// Pipelined HMMA GEMM: C = A(M,K) * B(N,K)^T, fp16 in, fp32 acc.
// CTA 128 x TN, BK=32, 3-stage cp.async, ldmatrix fragments.
// smem row stride 80B -> conflict-free. Split-K via blockIdx.z.
// EPI: 0 = none, 1 = softplus(C + bias).  OUTH: 1 = fp16 C, 0 = fp32 C.
// ---------------------------------------------------------------------------
template<int TN, int EPI, int OUTH>
__global__ __launch_bounds__(256, 1) void gemm_cp(
    const __half* __restrict__ A, int lda,
    const __half* __restrict__ Bm,
    const float* __restrict__ bias, void* __restrict__ Cbase,
    int M, int Nsz, int Kfull, int Ksub)
{
    constexpr int ABY = 128 * 80;
    constexpr int BBY = TN * 80;
    constexpr int STG = ABY + BBY;
    constexpr int JN  = TN / 32;

    extern __shared__ __align__(16) char smem[];
    const uint32_t sb0 = (uint32_t)__cvta_generic_to_shared(smem);

    const int tid = threadIdx.x, wid = tid >> 5, lid = tid & 31;
    const int bm = blockIdx.y * 128, bn = blockIdx.x * TN;
    const int koff = blockIdx.z * Ksub;
    const int wm = (wid & 1) * 64, wn = (wid >> 1) * (TN / 4);
    const int g = lid >> 2, t4 = lid & 3;
    const int S = Ksub >> 5;

    const int lr = lid & 7, tq = lid >> 3;
    const int a_ro = (tq & 1) * 8, a_co = (tq >> 1) * 16;
    const int b_ro = (tq >> 1) * 8, b_co = (tq & 1) * 16;

    auto issue = [&](int s) {
        const int k0 = koff + (s << 5);
        const uint32_t st = sb0 + (s % 3) * STG;
#pragma unroll
        for (int i = 0; i < 2; i++) {
            const int id = tid + i * 256, row = id >> 2, q = id & 3;
            const size_t go = (size_t)(bm + row) * lda + k0 + q * 8;
            cpa16(st + row * 80 + q * 16, A + go);
        }
#pragma unroll
        for (int i = 0; i < TN / 64; i++) {
            const int id = tid + i * 256, row = id >> 2, q = id & 3;
            const bool ok = (bn + row) < Nsz;
            const int r2 = ok ? (bn + row) : 0;
            const size_t go = (size_t)r2 * Kfull + k0 + q * 8;
            cpa16z(st + ABY + row * 80 + q * 16, Bm + go, ok);
        }
    };

    float acc[4][JN][4];
#pragma unroll
    for (int i = 0; i < 4; i++)
#pragma unroll
        for (int j = 0; j < JN; j++)
#pragma unroll
            for (int c = 0; c < 4; c++) acc[i][j][c] = 0.f;

    issue(0); CP_COMMIT();
    if (S > 1) issue(1);
    CP_COMMIT();

    for (int s = 0; s < S; s++) {
        CP_WAIT1();
        __syncthreads();
        if (s + 2 < S) issue(s + 2);
        CP_COMMIT();

        const uint32_t st = sb0 + (s % 3) * STG;
#pragma unroll
        for (int kk = 0; kk < 2; kk++) {
            const int cb = kk * 32;
            uint32_t ah[4][4];
#pragma unroll
            for (int i = 0; i < 4; i++)
                ldmx4(ah[i], st + (wm + i * 16 + a_ro + lr) * 80 + cb + a_co);
#pragma unroll
            for (int j2 = 0; j2 < JN / 2; j2++) {
                uint32_t bh[4];
                ldmx4(bh, st + ABY + (wn + j2 * 16 + b_ro + lr) * 80 + cb + b_co);
#pragma unroll
                for (int i = 0; i < 4; i++) {
                    mma16816(acc[i][2 * j2],     ah[i], bh);
                    mma16816(acc[i][2 * j2 + 1], ah[i], bh + 2);
                }
            }
        }
    }

#pragma unroll
    for (int i = 0; i < 4; i++) {
        const int r0 = bm + wm + i * 16 + g;
#pragma unroll
        for (int j = 0; j < JN; j++) {
            const int c = bn + wn + j * 8 + t4 * 2;
            if (c < Nsz) {
                float v0 = acc[i][j][0], v1 = acc[i][j][1];
                float v2 = acc[i][j][2], v3 = acc[i][j][3];
                if (EPI == 1) {
                    const float b0 = bias[c], b1 = bias[c + 1];
                    v0 += b0; v1 += b1; v2 += b0; v3 += b1;
                    v0 = (v0 > 20.f) ? v0 : log1pf(__expf(v0));
                    v1 = (v1 > 20.f) ? v1 : log1pf(__expf(v1));
                    v2 = (v2 > 20.f) ? v2 : log1pf(__expf(v2));
                    v3 = (v3 > 20.f) ? v3 : log1pf(__expf(v3));
                }
                if (OUTH) {
                    __half* C = (__half*)Cbase + (size_t)blockIdx.z * M * Nsz;
                    *(__half2*)(C + (size_t)r0 * Nsz + c) =
                        __floats2half2_rn(v0, v1);
                    *(__half2*)(C + (size_t)(r0 + 8) * Nsz + c) =
                        __floats2half2_rn(v2, v3);
                } else {
                    float* C = (float*)Cbase + (size_t)blockIdx.z * M * Nsz;
                    *(float2*)(C + (size_t)r0 * Nsz + c)       = make_float2(v0, v1);
                    *(float2*)(C + (size_t)(r0 + 8) * Nsz + c) = make_float2(v2, v3);
                }
            }
        }
    }
}

// ---------------------------------------------------------------------------
__global__ __launch_bounds__(256) void convert_w_kernel(
    const float* __restrict__ w, __half* __restrict__ o, int n)
{
    const int i = blockIdx.x * 256 + threadIdx.x;
    if (i < n) o[i] = __float2half_rn(w[i]);
}

__global__ __launch_bounds__(256) void reduce_xproj_kernel(
    const float* __restrict__ part, float* __restrict__ xdbl,
    __half* __restrict__ dth)
{
    const size_t n1 = (size_t)ROWS * XD;
    const size_t i = (size_t)blockIdx.x * 256 + threadIdx.x;
    float s = part[i] + part[i + n1] + part[i + 2 * n1] + part[i + 3 * n1];
    xdbl[i] = s;
    const int col = (int)(i % XD);
    if (col < DTR) dth[(i / XD) * DTR + col] = __float2half_rn(s);
}

// ---------------------------------------------------------------------------
// Depthwise causal conv (fp16 in) + bias + SiLU -> fp16 xh
// ---------------------------------------------------------------------------
__global__ __launch_bounds__(256) void conv_silu_kernel(
    const __half* __restrict__ xz, const float* __restrict__ w,
    const float* __restrict__ bias, __half* __restrict__ xh)
{
    const long i = (long)blockIdx.x * 256 + threadIdx.x;
    const int  d = (int)(i & (DI_ - 1));
    const long bl = i >> 11;
    const int  l = (int)(bl & (SEQ - 1));
    const long b = bl >> 10;

    const __half* base = xz + ((size_t)b * SEQ) * (2 * DI_) + d;
    float acc = bias[d];
    const float w0 = w[d * 4 + 0], w1 = w[d * 4 + 1], w2 = w[d * 4 + 2], w3 = w[d * 4 + 3];
    if (l >= 3) acc += w0 * __half2float(base[(size_t)(l - 3) * (2 * DI_)]);
    if (l >= 2) acc += w1 * __half2float(base[(size_t)(l - 2) * (2 * DI_)]);
    if (l >= 1) acc += w2 * __half2float(base[(size_t)(l - 1) * (2 * DI_)]);
    acc += w3 * __half2float(base[(size_t)l * (2 * DI_)]);
    xh[i] = __float2half_rn(acc / (1.f + __expf(-acc)));
}

// ---------------------------------------------------------------------------
// Selective scan (software pipelined), fp16 x/z inputs, fp16 y output.
// ---------------------------------------------------------------------------
__global__ __launch_bounds__(128) void scan_kernel(
    const float* __restrict__ dtb, const __half* __restrict__ xh,
    const float* __restrict__ xdbl, const __half* __restrict__ xz,
    const float* __restrict__ A_log, const float* __restrict__ Dp,
    __half* __restrict__ y)
{
    const int b = blockIdx.y;
    const int d = blockIdx.x * 128 + threadIdx.x;
    const int tid = threadIdx.x;

    float A[NST], h[NST];
#pragma unroll
    for (int n = 0; n < NST; n++) {
        A[n] = -__expf(A_log[d * NST + n]);
        h[n] = 0.f;
    }
    const float dval = Dp[d];

    __shared__ float sB[2][NST], sC[2][NST];
    const size_t rowbase = (size_t)b * SEQ;

    if (tid < 2 * NST) {
        for (int p = 0; p < 2; p++) {
            float v = xdbl[(rowbase + p) * XD + DTR + tid];
            if (tid < NST) sB[p][tid] = v; else sC[p][tid - NST] = v;
        }
    }
    float bc_next = 0.f;
    if (tid < 2 * NST) bc_next = xdbl[(rowbase + 2) * XD + DTR + tid];

    float dq[2], xq[2], zq[2];
#pragma unroll
    for (int p = 0; p < 2; p++) {
        const size_t idx = (rowbase + p) * DI_ + d;
        dq[p] = dtb[idx];
        xq[p] = __half2float(xh[idx]);
        zq[p] = __half2float(xz[(rowbase + p) * (2 * DI_) + DI_ + d]);
    }
    __syncthreads();

    for (int l = 0; l < SEQ; l++) {
        const int par = l & 1;
        const float dtv = dq[par], xv = xq[par], zv = zq[par];

        const int lp = (l + 2 < SEQ) ? l + 2 : SEQ - 1;
        const size_t idx2 = (rowbase + lp) * DI_ + d;
        dq[par] = dtb[idx2];
        xq[par] = __half2float(xh[idx2]);
        zq[par] = __half2float(xz[(rowbase + lp) * (2 * DI_) + DI_ + d]);

        const float dx = dtv * xv;
        float acc = 0.f;
#pragma unroll
        for (int n = 0; n < NST; n++) {
            h[n] = __expf(dtv * A[n]) * h[n] + dx * sB[par][n];
            acc += h[n] * sC[par][n];
        }
        acc += xv * dval;
        acc *= zv / (1.f + __expf(-zv));

        y[(rowbase + l) * DI_ + d] = __float2half_rn(acc);

        __syncthreads();
        if (tid < 2 * NST) {
            if (tid < NST) sB[par][tid] = bc_next; else sC[par][tid - NST] = bc_next;
            const int lq = (l + 3 < SEQ) ? l + 3 : SEQ - 1;
            bc_next = xdbl[(rowbase + lq) * XD + DTR + tid];
        }
    }
}

// ---------------------------------------------------------------------------
__device__ __forceinline__ float block_sum256(float v)
{
    __shared__ float red[8];
    const int lane = threadIdx.x & 31, w = threadIdx.x >> 5;
#pragma unroll
    for (int o = 16; o; o >>= 1) v += __shfl_xor_sync(0xffffffffu, v, o);
    if (!lane) red[w] = v;
    __syncthreads();
    if (w == 0) {
        v = (lane < 8) ? red[lane] : 0.f;
#pragma unroll
        for (int o = 4; o; o >>= 1) v += __shfl_xor_sync(0xffffffffu, v, o);
        if (!lane) red[0] = v;
    }
    __syncthreads();
    return red[0];
}

__global__ __launch_bounds__(256) void rms_mix_tm_kernel(
    const float* __restrict__ residual, const float* __restrict__ hstm,
    const float* __restrict__ hscm, const float* __restrict__ nw,
    const float* __restrict__ wavg, float* __restrict__ res1,
    __half* __restrict__ omix)
{
    const int bs = blockIdx.x, b = bs >> 10, s = bs & 1023, t = threadIdx.x;
    const size_t r4 = (size_t)bs * 256 + t;
    const size_t i0 = ((size_t)(b * 2 + 0) * 1024 + s) * 256 + t;
    const size_t i1 = ((size_t)(b * 2 + 1) * 1024 + s) * 256 + t;

    float4 r  = ((const float4*)residual)[r4];
    float4 c1 = ((const float4*)hscm)[i1];
    r.x += c1.x; r.y += c1.y; r.z += c1.z; r.w += c1.w;
    ((float4*)res1)[r4] = r;

    const float tot = block_sum256(r.x * r.x + r.y * r.y + r.z * r.z + r.w * r.w);
    const float scale = rsqrtf(tot * (1.f / (float)DM) + 1e-5f);

    float w0 = wavg[s], w1 = wavg[1024 + s], w2 = wavg[2048 + s], w3 = wavg[3072 + s];
    const float mx = fmaxf(fmaxf(w0, w1), fmaxf(w2, w3));
    w0 = __expf(w0 - mx); w1 = __expf(w1 - mx); w2 = __expf(w2 - mx); w3 = __expf(w3 - mx);
    const float inv = 1.f / (w0 + w1 + w2 + w3);
    w0 *= inv; w1 *= inv; w2 *= inv; w3 *= inv;

    const float4 a0 = ((const float4*)hstm)[i0];
    const float4 a1 = ((const float4*)hstm)[i1];
    const float4 c0 = ((const float4*)hscm)[i0];
    const float4 wn = ((const float4*)nw)[t];
    float o0 = w0 * a0.x + w1 * a1.x + w2 * c0.x + w3 * (r.x * scale * wn.x);
    float o1 = w0 * a0.y + w1 * a1.y + w2 * c0.y + w3 * (r.y * scale * wn.y);
    float o2 = w0 * a0.z + w1 * a1.z + w2 * c0.z + w3 * (r.z * scale * wn.z);
    float o3 = w0 * a0.w + w1 * a1.w + w2 * c0.w + w3 * (r.w * scale * wn.w);
    __half2* op = (__half2*)(omix + r4 * 4);
    op[0] = __floats2half2_rn(o0, o1);
    op[1] = __floats2half2_rn(o2, o3);
}

__global__ __launch_bounds__(256) void rms_mix_cm_kernel(
    const float* __restrict__ res1, const float* __restrict__ outm,
    const float* __restrict__ hstm, const float* __restrict__ hscm,
    const float* __restrict__ nw, const float* __restrict__ wavg,
    float* __restrict__ res2, float* __restrict__ hmix)
{
    const int bs = blockIdx.x, b = bs >> 10, s = bs & 1023, t = threadIdx.x;
    const size_t r4 = (size_t)bs * 256 + t;
    const size_t i0 = ((size_t)(b * 2 + 0) * 1024 + s) * 256 + t;
    const size_t i1 = ((size_t)(b * 2 + 1) * 1024 + s) * 256 + t;

    float4 r  = ((const float4*)res1)[r4];
    float4 om = ((const float4*)outm)[r4];
    r.x += om.x; r.y += om.y; r.z += om.z; r.w += om.w;
    ((float4*)res2)[r4] = r;

    const float tot = block_sum256(r.x * r.x + r.y * r.y + r.z * r.z + r.w * r.w);
    const float scale = rsqrtf(tot * (1.f / (float)DM) + 1e-5f);

    float w[5];
#pragma unroll
    for (int n = 0; n < 5; n++) w[n] = wavg[n * 1024 + s];
    float mx = w[0];
#pragma unroll
    for (int n = 1; n < 5; n++) mx = fmaxf(mx, w[n]);
    float sum = 0.f;
#pragma unroll
    for (int n = 0; n < 5; n++) { w[n] = __expf(w[n] - mx); sum += w[n]; }
    const float inv = 1.f / sum;
#pragma unroll
    for (int n = 0; n < 5; n++) w[n] *= inv;

    const float4 a0 = ((const float4*)hstm)[i0];
    const float4 a1 = ((const float4*)hstm)[i1];
    const float4 c0 = ((const float4*)hscm)[i0];
    const float4 c1 = ((const float4*)hscm)[i1];
    const float4 wn = ((const float4*)nw)[t];
    float4 o;
    o.x = w[0]*a0.x + w[1]*a1.x + w[2]*(r.x*scale*wn.x) + w[3]*c0.x + w[4]*c1.x;
    o.y = w[0]*a0.y + w[1]*a1.y + w[2]*(r.y*scale*wn.y) + w[3]*c0.y + w[4]*c1.y;
    o.z = w[0]*a0.z + w[1]*a1.z + w[2]*(r.z*scale*wn.z) + w[3]*c0.z + w[4]*c1.z;
    o.w = w[0]*a0.w + w[1]*a1.w + w[2]*(r.w*scale*wn.w) + w[3]*c0.w + w[4]*c1.w;
    ((float4*)hmix)[r4] = o;
}

// transpose fp32 -> fp16
__global__ __launch_bounds__(256) void transpose_h_kernel(
    const float* __restrict__ in, __half* __restrict__ o)
{
    __shared__ float tile[32][33];
    const int b = blockIdx.z;
    const int r0 = blockIdx.y * 32, c0 = blockIdx.x * 32;
    const size_t base = (size_t)b * 1024 * 1024;
#pragma unroll
    for (int i = threadIdx.y; i < 32; i += 8)
        tile[i][threadIdx.x] = in[base + (size_t)(r0 + i) * 1024 + c0 + threadIdx.x];
    __syncthreads();
#pragma unroll
    for (int i = threadIdx.y; i < 32; i += 8)
        o[base + (size_t)(c0 + i) * 1024 + r0 + threadIdx.x] =
            __float2half_rn(tile[threadIdx.x][i]);
}

// transpose fp32 -> fp32 (final output)
__global__ __launch_bounds__(256) void transpose_kernel(
    const float* __restrict__ in, float* __restrict__ out)
{
    __shared__ float tile[32][33];
    const int b = blockIdx.z;
    const int r0 = blockIdx.y * 32, c0 = blockIdx.x * 32;
    const size_t base = (size_t)b * 1024 * 1024;
#pragma unroll
    for (int i = threadIdx.y; i < 32; i += 8)
        tile[i][threadIdx.x] = in[base + (size_t)(r0 + i) * 1024 + c0 + threadIdx.x];
    __syncthreads();
#pragma unroll
    for (int i = threadIdx.y; i < 32; i += 8)
        out[base + (size_t)(c0 + i) * 1024 + r0 + threadIdx.x] = tile[threadIdx.x][i];
}

// ---------------------------------------------------------------------------
// host side
// ---------------------------------------------------------------------------
static const int SMEM256 = 3 * (128 * 80 + 256 * 80);   // 92160
static const int SMEM128 = 3 * (128 * 80 + 128 * 80);   // 61440

struct Bufs {
    float *dtb, *xdbl, *xpart, *res1, *hmix, *outm;
    __half *xzh, *xh16, *y16, *dth, *mix16, *wh;
};

static void conv_w16(const float* w, __half* o, int n)
{
    convert_w_kernel<<<(n + 255) / 256, 256>>>(w, o, n);
}

// mix16 holds the fp16 A operand for in_proj on entry
static void run_mamba(const Bufs& B, const float* const* P, float* out)
{
    const float* in_w   = P[0];
    const float* conv_w = P[1];
    const float* conv_b = P[2];
    const float* xproj  = P[3];
    const float* dt_w   = P[4];
    const float* dt_b   = P[5];
    const float* A_log  = P[6];
    const float* Dp     = P[7];
    const float* out_w  = P[8];

    conv_w16(in_w, B.wh, 2 * DI_ * DM);
    gemm_cp<256, 0, 1><<<dim3(2 * DI_ / 256, ROWS / 128, 1), 256, SMEM256>>>(
        B.mix16, DM, B.wh, nullptr, B.xzh, ROWS, 2 * DI_, DM, DM);

    conv_silu_kernel<<<(ROWS * DI_) / 256, 256>>>(B.xzh, conv_w, conv_b, B.xh16);

    conv_w16(xproj, B.wh, XD * DI_);
    gemm_cp<128, 0, 0><<<dim3(1, ROWS / 128, KSP), 256, SMEM128>>>(
        B.xh16, DI_, B.wh, nullptr, B.xpart, ROWS, XD, DI_, DI_ / KSP);
    reduce_xproj_kernel<<<(ROWS * XD) / 256, 256>>>(B.xpart, B.xdbl, B.dth);

    conv_w16(dt_w, B.wh, DI_ * DTR);
    gemm_cp<256, 1, 0><<<dim3(DI_ / 256, ROWS / 128, 1), 256, SMEM256>>>(
        B.dth, DTR, B.wh, dt_b, B.dtb, ROWS, DI_, DTR, DTR);

    scan_kernel<<<dim3(DI_ / 128, BSZ), 128>>>(B.dtb, B.xh16, B.xdbl, B.xzh,
                                               A_log, Dp, B.y16);

    conv_w16(out_w, B.wh, DM * DI_);
    gemm_cp<256, 0, 0><<<dim3(DM / 256, ROWS / 128, 1), 256, SMEM256>>>(
        B.y16, DI_, B.wh, nullptr, out, ROWS, DM, DI_, DI_);
}

extern "C" void kernel_launch(void* const* d_in, const int* in_sizes, int n_in,
                              void* d_out, int out_size)
{
    cudaFuncSetAttribute(gemm_cp<256, 0, 1>, cudaFuncAttributeMaxDynamicSharedMemorySize, SMEM256);
    cudaFuncSetAttribute(gemm_cp<256, 0, 0>, cudaFuncAttributeMaxDynamicSharedMemorySize, SMEM256);
    cudaFuncSetAttribute(gemm_cp<256, 1, 0>, cudaFuncAttributeMaxDynamicSharedMemorySize, SMEM256);
    cudaFuncSetAttribute(gemm_cp<128, 0, 0>, cudaFuncAttributeMaxDynamicSharedMemorySize, SMEM128);

    const float* hstm     = (const float*)d_in[0];
    const float* hscm     = (const float*)d_in[1];
    const float* residual = (const float*)d_in[2];
    const float* norm_tm  = (const float*)d_in[3];
    const float* wavg_tm  = (const float*)d_in[4];

    const float *norm_cm, *wavg_cm;
    int btm;
    const int bcm = 16;
    if (in_sizes[5] == 1024) {            // dict order
        norm_cm = (const float*)d_in[5];
        wavg_cm = (const float*)d_in[6];
        btm = 7;
    } else {                              // signature order
        btm = 5;
        norm_cm = (const float*)d_in[14];
        wavg_cm = (const float*)d_in[15];
    }
    const float* P_tm[9];
    const float* P_cm[9];
    for (int i = 0; i < 9; i++) {
        P_tm[i] = (const float*)d_in[btm + i];
        P_cm[i] = (const float*)d_in[bcm + i];
    }

    Bufs B;
    cudaGetSymbolAddress((void**)&B.dtb,   g_dt);
    cudaGetSymbolAddress((void**)&B.xdbl,  g_xdbl);
    cudaGetSymbolAddress((void**)&B.xpart, g_xpart);
    cudaGetSymbolAddress((void**)&B.res1,  g_res1);
    cudaGetSymbolAddress((void**)&B.hmix,  g_hmix);
    cudaGetSymbolAddress((void**)&B.outm,  g_outm);
    cudaGetSymbolAddress((void**)&B.xzh,   g_xzh);
    cudaGetSymbolAddress((void**)&B.xh16,  g_xh16);
    cudaGetSymbolAddress((void**)&B.y16,   g_y16);
    cudaGetSymbolAddress((void**)&B.dth,   g_dth);
    cudaGetSymbolAddress((void**)&B.mix16, g_mix16);
    cudaGetSymbolAddress((void**)&B.wh,    g_wh);

    float* dout = (float*)d_out;
    const long total = (long)BSZ * SEQ * DM;
    float* res2_out = (out_size >= 2 * total) ? (dout + total) : B.res1;

    // --- token-mixer path ---
    rms_mix_tm_kernel<<<ROWS, 256>>>(residual, hstm, hscm, norm_tm, wavg_tm,
                                     B.res1, B.mix16);
    run_mamba(B, P_tm, B.outm);

    // --- channel-mixer path ---
    rms_mix_cm_kernel<<<ROWS, 256>>>(B.res1, B.outm, hstm, hscm, norm_cm, wavg_cm,
                                     res2_out, B.hmix);
    transpose_h_kernel<<<dim3(32, 32, BSZ), dim3(32, 8)>>>(B.hmix, B.mix16);
    run_mamba(B, P_cm, B.outm);
    transpose_kernel<<<dim3(32, 32, BSZ), dim3(32, 8)>>>(B.outm, dout);
}

// round 7
// speedup vs baseline: 1.6660x; 1.0829x over previous
#include <cuda_runtime.h>
#include <cuda_fp16.h>
#include <cstdint>
#include <math.h>

// ---------------------------------------------------------------------------
// SambaMixerBlock: B=8, S=D=1024, N=16, DCONV=4, EXPAND=2 -> DI=2048, DT_RANK=64
// Round 7: non-GEMM attack. Warp-autonomous scan with single-exp power trick
//          (guarded), fused weight conversion, half2 conv.
// ---------------------------------------------------------------------------

#define BSZ   8
#define SEQ   1024
#define DM    1024
#define DI_   2048
#define NST   16
#define DTR   64
#define XD    96
#define ROWS  (BSZ*SEQ)
#define KSP   4                      // x_proj split-K factor

// fp32 scratch
__device__ float g_dt  [(size_t)ROWS * DI_];
__device__ float g_xdbl[(size_t)ROWS * XD];
__device__ float g_xpart[(size_t)KSP * ROWS * XD];
__device__ float g_res1[(size_t)ROWS * DM];
__device__ float g_hmix[(size_t)ROWS * DM];
__device__ float g_outm[(size_t)ROWS * DM];
// fp16 scratch
__device__ __half g_xzh [(size_t)ROWS * 2 * DI_];
__device__ __half g_xh16[(size_t)ROWS * DI_];
__device__ __half g_y16 [(size_t)ROWS * DI_];
__device__ __half g_dth [(size_t)ROWS * DTR];
__device__ __half g_mix16[(size_t)ROWS * DM];

// converted weights: per path IN | XPROJ | DT | OUT
#define W_IN   0
#define W_XP   (2 * DI_ * DM)                    // 4194304
#define W_DT   (W_XP + XD * DI_)                 // +196608
#define W_OUT  (W_DT + DI_ * DTR)                // +131072
#define W_STRIDE (W_OUT + DM * DI_)              // 6619136
__device__ __half g_wh[(size_t)2 * W_STRIDE];

// ---------------------------------------------------------------------------
__device__ __forceinline__ void cpa16(uint32_t d, const void* s)
{
    asm volatile("cp.async.cg.shared.global [%0], [%1], 16;" :: "r"(d), "l"(s));
}
__device__ __forceinline__ void cpa16z(uint32_t d, const void* s, bool ok)
{
    int sz = ok ? 16 : 0;
    asm volatile("cp.async.cg.shared.global [%0], [%1], 16, %2;"
                 :: "r"(d), "l"(s), "r"(sz));
}
#define CP_COMMIT() asm volatile("cp.async.commit_group;" ::: "memory")
#define CP_WAIT1()  asm volatile("cp.async.wait_group 1;" ::: "memory")

__device__ __forceinline__ void mma16816(float* d, const uint32_t* a, const uint32_t* b)
{
    asm volatile(
        "mma.sync.aligned.m16n8k16.row.col.f32.f16.f16.f32 "
        "{%0,%1,%2,%3}, {%4,%5,%6,%7}, {%8,%9}, {%0,%1,%2,%3};"
        : "+f"(d[0]), "+f"(d[1]), "+f"(d[2]), "+f"(d[3])
        : "r"(a[0]), "r"(a[1]), "r"(a[2]), "r"(a[3]), "r"(b[0]), "r"(b[1]));
}

__device__ __forceinline__ void ldmx4(uint32_t* r, uint32_t addr)
{
    asm volatile("ldmatrix.sync.aligned.m8n8.x4.shared.b16 {%0,%1,%2,%3}, [%4];"
                 : "=r"(r[0]), "=r"(r[1]), "=r"(r[2]), "=r"(r[3]) : "r"(addr));
}

// ---------------------------------------------------------------------------
// Pipelined HMMA GEMM (round 6, unchanged): C = A(M,K) * B(N,K)^T, fp16 in,
// fp32 acc. CTA 128 x TN, BK=32, 3-stage cp.async, ldmatrix. 80B row stride.
// EPI: 1 = softplus(C + bias). OUTH: 1 = fp16 C.
// ---------------------------------------------------------------------------
template<int TN, int EPI, int OUTH>
__global__ __launch_bounds__(256, 1) void gemm_cp(
    const __half* __restrict__ A, int lda,
    const __half* __restrict__ Bm,
    const float* __restrict__ bias, void* __restrict__ Cbase,
    int M, int Nsz, int Kfull, int Ksub)
{
    constexpr int ABY = 128 * 80;
    constexpr int BBY = TN * 80;
    constexpr int STG = ABY + BBY;
    constexpr int JN  = TN / 32;

    extern __shared__ __align__(16) char smem[];
    const uint32_t sb0 = (uint32_t)__cvta_generic_to_shared(smem);

    const int tid = threadIdx.x, wid = tid >> 5, lid = tid & 31;
    const int bm = blockIdx.y * 128, bn = blockIdx.x * TN;
    const int koff = blockIdx.z * Ksub;
    const int wm = (wid & 1) * 64, wn = (wid >> 1) * (TN / 4);
    const int g = lid >> 2, t4 = lid & 3;
    const int S = Ksub >> 5;

    const int lr = lid & 7, tq = lid >> 3;
    const int a_ro = (tq & 1) * 8, a_co = (tq >> 1) * 16;
    const int b_ro = (tq >> 1) * 8, b_co = (tq & 1) * 16;

    auto issue = [&](int s) {
        const int k0 = koff + (s << 5);
        const uint32_t st = sb0 + (s % 3) * STG;
#pragma unroll
        for (int i = 0; i < 2; i++) {
            const int id = tid + i * 256, row = id >> 2, q = id & 3;
            const size_t go = (size_t)(bm + row) * lda + k0 + q * 8;
            cpa16(st + row * 80 + q * 16, A + go);
        }
#pragma unroll
        for (int i = 0; i < TN / 64; i++) {
            const int id = tid + i * 256, row = id >> 2, q = id & 3;
            const bool ok = (bn + row) < Nsz;
            const int r2 = ok ? (bn + row) : 0;
            const size_t go = (size_t)r2 * Kfull + k0 + q * 8;
            cpa16z(st + ABY + row * 80 + q * 16, Bm + go, ok);
        }
    };

    float acc[4][JN][4];
#pragma unroll
    for (int i = 0; i < 4; i++)
#pragma unroll
        for (int j = 0; j < JN; j++)
#pragma unroll
            for (int c = 0; c < 4; c++) acc[i][j][c] = 0.f;

    issue(0); CP_COMMIT();
    if (S > 1) issue(1);
    CP_COMMIT();

    for (int s = 0; s < S; s++) {
        CP_WAIT1();
        __syncthreads();
        if (s + 2 < S) issue(s + 2);
        CP_COMMIT();

        const uint32_t st = sb0 + (s % 3) * STG;
#pragma unroll
        for (int kk = 0; kk < 2; kk++) {
            const int cb = kk * 32;
            uint32_t ah[4][4];
#pragma unroll
            for (int i = 0; i < 4; i++)
                ldmx4(ah[i], st + (wm + i * 16 + a_ro + lr) * 80 + cb + a_co);
#pragma unroll
            for (int j2 = 0; j2 < JN / 2; j2++) {
                uint32_t bh[4];
                ldmx4(bh, st + ABY + (wn + j2 * 16 + b_ro + lr) * 80 + cb + b_co);
#pragma unroll
                for (int i = 0; i < 4; i++) {
                    mma16816(acc[i][2 * j2],     ah[i], bh);
                    mma16816(acc[i][2 * j2 + 1], ah[i], bh + 2);
                }
            }
        }
    }

#pragma unroll
    for (int i = 0; i < 4; i++) {
        const int r0 = bm + wm + i * 16 + g;
#pragma unroll
        for (int j = 0; j < JN; j++) {
            const int c = bn + wn + j * 8 + t4 * 2;
            if (c < Nsz) {
                float v0 = acc[i][j][0], v1 = acc[i][j][1];
                float v2 = acc[i][j][2], v3 = acc[i][j][3];
                if (EPI == 1) {
                    const float b0 = bias[c], b1 = bias[c + 1];
                    v0 += b0; v1 += b1; v2 += b0; v3 += b1;
                    v0 = (v0 > 20.f) ? v0 : log1pf(__expf(v0));
                    v1 = (v1 > 20.f) ? v1 : log1pf(__expf(v1));
                    v2 = (v2 > 20.f) ? v2 : log1pf(__expf(v2));
                    v3 = (v3 > 20.f) ? v3 : log1pf(__expf(v3));
                }
                if (OUTH) {
                    __half* C = (__half*)Cbase + (size_t)blockIdx.z * M * Nsz;
                    *(__half2*)(C + (size_t)r0 * Nsz + c) = __floats2half2_rn(v0, v1);
                    *(__half2*)(C + (size_t)(r0 + 8) * Nsz + c) = __floats2half2_rn(v2, v3);
                } else {
                    float* C = (float*)Cbase + (size_t)blockIdx.z * M * Nsz;
                    *(float2*)(C + (size_t)r0 * Nsz + c)       = make_float2(v0, v1);
                    *(float2*)(C + (size_t)(r0 + 8) * Nsz + c) = make_float2(v2, v3);
                }
            }
        }
    }
}

// ---------------------------------------------------------------------------
// fused weight conversion: all 8 tensors, one launch, grid-stride per segment
// ---------------------------------------------------------------------------
struct WSeg { const float* src; __half* dst; int n; };
struct W8   { WSeg s[8]; };

__global__ __launch_bounds__(256) void convert_all_kernel(W8 segs)
{
    const int stride = gridDim.x * 256;
    const int t0 = blockIdx.x * 256 + threadIdx.x;
#pragma unroll
    for (int k = 0; k < 8; k++) {
        const float* src = segs.s[k].src;
        __half* dst = segs.s[k].dst;
        const int n = segs.s[k].n;
        for (int i = t0; i < n; i += stride)
            dst[i] = __float2half_rn(src[i]);
    }
}

__global__ __launch_bounds__(256) void reduce_xproj_kernel(
    const float* __restrict__ part, float* __restrict__ xdbl,
    __half* __restrict__ dth)
{
    const size_t n1 = (size_t)ROWS * XD;
    const size_t i = (size_t)blockIdx.x * 256 + threadIdx.x;
    float s = part[i] + part[i + n1] + part[i + 2 * n1] + part[i + 3 * n1];
    xdbl[i] = s;
    const int col = (int)(i % XD);
    if (col < DTR) dth[(i / XD) * DTR + col] = __float2half_rn(s);
}

// ---------------------------------------------------------------------------
// Depthwise causal conv + bias + SiLU, 2 channels/thread (half2)
// ---------------------------------------------------------------------------
__global__ __launch_bounds__(256) void conv_silu_kernel(
    const __half* __restrict__ xz, const float* __restrict__ w,
    const float* __restrict__ bias, __half* __restrict__ xh)
{
    const long i = (long)blockIdx.x * 256 + threadIdx.x;   // over ROWS*DI/2
    const int  d2 = (int)(i & (DI_ / 2 - 1));
    const int  d  = d2 * 2;
    const long bl = i >> 10;
    const int  l = (int)(bl & (SEQ - 1));
    const long b = bl >> 10;

    const __half* base = xz + ((size_t)b * SEQ) * (2 * DI_) + d;
    const float2 bs = *(const float2*)(bias + d);
    float a0 = bs.x, a1 = bs.y;
    const float4 wa = *(const float4*)(w + d * 4);
    const float4 wb = *(const float4*)(w + d * 4 + 4);

    __half2 v;
    float2 f;
    if (l >= 3) { v = *(const __half2*)(base + (size_t)(l - 3) * (2 * DI_));
                  f = __half22float2(v); a0 += wa.x * f.x; a1 += wb.x * f.y; }
    if (l >= 2) { v = *(const __half2*)(base + (size_t)(l - 2) * (2 * DI_));
                  f = __half22float2(v); a0 += wa.y * f.x; a1 += wb.y * f.y; }
    if (l >= 1) { v = *(const __half2*)(base + (size_t)(l - 1) * (2 * DI_));
                  f = __half22float2(v); a0 += wa.z * f.x; a1 += wb.z * f.y; }
    v = *(const __half2*)(base + (size_t)l * (2 * DI_));
    f = __half22float2(v); a0 += wa.w * f.x; a1 += wb.w * f.y;

    a0 = a0 / (1.f + __expf(-a0));
    a1 = a1 / (1.f + __expf(-a1));
    *(__half2*)(xh + bl * DI_ + d) = __floats2half2_rn(a0, a1);
}

// ---------------------------------------------------------------------------
// Selective scan: 1 warp per block (no bar.sync), B/C via register queue +
// shuffles, single-exp power trick (guarded exact fast path).
// ---------------------------------------------------------------------------
__global__ __launch_bounds__(32) void scan_kernel(
    const float* __restrict__ dtb, const __half* __restrict__ xh,
    const float* __restrict__ xdbl, const __half* __restrict__ xz,
    const float* __restrict__ A_log, const float* __restrict__ Dp,
    __half* __restrict__ y)
{
    const int b = blockIdx.y;
    const int lane = threadIdx.x;
    const int d = blockIdx.x * 32 + lane;

    float A[NST], h[NST];
#pragma unroll
    for (int n = 0; n < NST; n++) {
        A[n] = -__expf(A_log[d * NST + n]);
        h[n] = 0.f;
    }
    const float A0 = A[0];
    bool uni = true;
#pragma unroll
    for (int n = 1; n < NST; n++)
        uni = uni && (fabsf(A[n] - (n + 1) * A0) <= 1e-3f * (n + 1) * fabsf(A0) + 1e-12f);
    const float dval = Dp[d];

    const size_t rowbase = (size_t)b * SEQ;

    float  dq[4], bcq[4];
    __half xq[4], zq[4];
#pragma unroll
    for (int p = 0; p < 4; p++) {
        const size_t idx = (rowbase + p) * DI_ + d;
        dq[p]  = dtb[idx];
        xq[p]  = xh[idx];
        zq[p]  = xz[(rowbase + p) * (2 * DI_) + DI_ + d];
        bcq[p] = xdbl[(rowbase + p) * XD + DTR + lane];
    }

    for (int l = 0; l < SEQ; l++) {
        const int sl = l & 3;
        const float dtv = dq[sl];
        const float xv = __half2float(xq[sl]);
        const float zv = __half2float(zq[sl]);
        const float bcv = bcq[sl];

        const int lp = (l + 4 < SEQ) ? l + 4 : SEQ - 1;
        const size_t idx2 = (rowbase + lp) * DI_ + d;
        dq[sl]  = dtb[idx2];
        xq[sl]  = xh[idx2];
        zq[sl]  = xz[(rowbase + lp) * (2 * DI_) + DI_ + d];
        bcq[sl] = xdbl[(rowbase + lp) * XD + DTR + lane];

        const float dx = dtv * xv;
        float acc = 0.f;
        if (uni) {
            const float p1 = __expf(dtv * A0);
            float e[NST];
            e[0] = p1;
            e[1] = p1 * p1;
            e[2] = e[1] * p1;
            e[3] = e[1] * e[1];
#pragma unroll
            for (int n = 4; n < NST; n++) e[n] = e[n - 4] * e[3];
#pragma unroll
            for (int n = 0; n < NST; n++) {
                const float Bn = __shfl_sync(0xffffffffu, bcv, n);
                const float Cn = __shfl_sync(0xffffffffu, bcv, 16 + n);
                h[n] = e[n] * h[n] + dx * Bn;
                acc += h[n] * Cn;
            }
        } else {
#pragma unroll
            for (int n = 0; n < NST; n++) {
                const float Bn = __shfl_sync(0xffffffffu, bcv, n);
                const float Cn = __shfl_sync(0xffffffffu, bcv, 16 + n);
                h[n] = __expf(dtv * A[n]) * h[n] + dx * Bn;
                acc += h[n] * Cn;
            }
        }
        acc += xv * dval;
        acc *= zv / (1.f + __expf(-zv));
        y[(rowbase + l) * DI_ + d] = __float2half_rn(acc);
    }
}

// ---------------------------------------------------------------------------
__device__ __forceinline__ float block_sum256(float v)
{
    __shared__ float red[8];
    const int lane = threadIdx.x & 31, w = threadIdx.x >> 5;
#pragma unroll
    for (int o = 16; o; o >>= 1) v += __shfl_xor_sync(0xffffffffu, v, o);
    if (!lane) red[w] = v;
    __syncthreads();
    if (w == 0) {
        v = (lane < 8) ? red[lane] : 0.f;
#pragma unroll
        for (int o = 4; o; o >>= 1) v += __shfl_xor_sync(0xffffffffu, v, o);
        if (!lane) red[0] = v;
    }
    __syncthreads();
    return red[0];
}

__global__ __launch_bounds__(256) void rms_mix_tm_kernel(
    const float* __restrict__ residual, const float* __restrict__ hstm,
    const float* __restrict__ hscm, const float* __restrict__ nw,
    const float* __restrict__ wavg, float* __restrict__ res1,
    __half* __restrict__ omix)
{
    const int bs = blockIdx.x, b = bs >> 10, s = bs & 1023, t = threadIdx.x;
    const size_t r4 = (size_t)bs * 256 + t;
    const size_t i0 = ((size_t)(b * 2 + 0) * 1024 + s) * 256 + t;
    const size_t i1 = ((size_t)(b * 2 + 1) * 1024 + s) * 256 + t;

    float4 r  = ((const float4*)residual)[r4];
    float4 c1 = ((const float4*)hscm)[i1];
    r.x += c1.x; r.y += c1.y; r.z += c1.z; r.w += c1.w;
    ((float4*)res1)[r4] = r;

    const float tot = block_sum256(r.x * r.x + r.y * r.y + r.z * r.z + r.w * r.w);
    const float scale = rsqrtf(tot * (1.f / (float)DM) + 1e-5f);

    float w0 = wavg[s], w1 = wavg[1024 + s], w2 = wavg[2048 + s], w3 = wavg[3072 + s];
    const float mx = fmaxf(fmaxf(w0, w1), fmaxf(w2, w3));
    w0 = __expf(w0 - mx); w1 = __expf(w1 - mx); w2 = __expf(w2 - mx); w3 = __expf(w3 - mx);
    const float inv = 1.f / (w0 + w1 + w2 + w3);
    w0 *= inv; w1 *= inv; w2 *= inv; w3 *= inv;

    const float4 a0 = ((const float4*)hstm)[i0];
    const float4 a1 = ((const float4*)hstm)[i1];
    const float4 c0 = ((const float4*)hscm)[i0];
    const float4 wn = ((const float4*)nw)[t];
    float o0 = w0 * a0.x + w1 * a1.x + w2 * c0.x + w3 * (r.x * scale * wn.x);
    float o1 = w0 * a0.y + w1 * a1.y + w2 * c0.y + w3 * (r.y * scale * wn.y);
    float o2 = w0 * a0.z + w1 * a1.z + w2 * c0.z + w3 * (r.z * scale * wn.z);
    float o3 = w0 * a0.w + w1 * a1.w + w2 * c0.w + w3 * (r.w * scale * wn.w);
    __half2* op = (__half2*)(omix + r4 * 4);
    op[0] = __floats2half2_rn(o0, o1);
    op[1] = __floats2half2_rn(o2, o3);
}

__global__ __launch_bounds__(256) void rms_mix_cm_kernel(
    const float* __restrict__ res1, const float* __restrict__ outm,
    const float* __restrict__ hstm, const float* __restrict__ hscm,
    const float* __restrict__ nw, const float* __restrict__ wavg,
    float* __restrict__ res2, float* __restrict__ hmix)
{
    const int bs = blockIdx.x, b = bs >> 10, s = bs & 1023, t = threadIdx.x;
    const size_t r4 = (size_t)bs * 256 + t;
    const size_t i0 = ((size_t)(b * 2 + 0) * 1024 + s) * 256 + t;
    const size_t i1 = ((size_t)(b * 2 + 1) * 1024 + s) * 256 + t;

    float4 r  = ((const float4*)res1)[r4];
    float4 om = ((const float4*)outm)[r4];
    r.x += om.x; r.y += om.y; r.z += om.z; r.w += om.w;
    ((float4*)res2)[r4] = r;

    const float tot = block_sum256(r.x * r.x + r.y * r.y + r.z * r.z + r.w * r.w);
    const float scale = rsqrtf(tot * (1.f / (float)DM) + 1e-5f);

    float w[5];
#pragma unroll
    for (int n = 0; n < 5; n++) w[n] = wavg[n * 1024 + s];
    float mx = w[0];
#pragma unroll
    for (int n = 1; n < 5; n++) mx = fmaxf(mx, w[n]);
    float sum = 0.f;
#pragma unroll
    for (int n = 0; n < 5; n++) { w[n] = __expf(w[n] - mx); sum += w[n]; }
    const float inv = 1.f / sum;
#pragma unroll
    for (int n = 0; n < 5; n++) w[n] *= inv;

    const float4 a0 = ((const float4*)hstm)[i0];
    const float4 a1 = ((const float4*)hstm)[i1];
    const float4 c0 = ((const float4*)hscm)[i0];
    const float4 c1 = ((const float4*)hscm)[i1];
    const float4 wn = ((const float4*)nw)[t];
    float4 o;
    o.x = w[0]*a0.x + w[1]*a1.x + w[2]*(r.x*scale*wn.x) + w[3]*c0.x + w[4]*c1.x;
    o.y = w[0]*a0.y + w[1]*a1.y + w[2]*(r.y*scale*wn.y) + w[3]*c0.y + w[4]*c1.y;
    o.z = w[0]*a0.z + w[1]*a1.z + w[2]*(r.z*scale*wn.z) + w[3]*c0.z + w[4]*c1.z;
    o.w = w[0]*a0.w + w[1]*a1.w + w[2]*(r.w*scale*wn.w) + w[3]*c0.w + w[4]*c1.w;
    ((float4*)hmix)[r4] = o;
}

__global__ __launch_bounds__(256) void transpose_h_kernel(
    const float* __restrict__ in, __half* __restrict__ o)
{
    __shared__ float tile[32][33];
    const int b = blockIdx.z;
    const int r0 = blockIdx.y * 32, c0 = blockIdx.x * 32;
    const size_t base = (size_t)b * 1024 * 1024;
#pragma unroll
    for (int i = threadIdx.y; i < 32; i += 8)
        tile[i][threadIdx.x] = in[base + (size_t)(r0 + i) * 1024 + c0 + threadIdx.x];
    __syncthreads();
#pragma unroll
    for (int i = threadIdx.y; i < 32; i += 8)
        o[base + (size_t)(c0 + i) * 1024 + r0 + threadIdx.x] =
            __float2half_rn(tile[threadIdx.x][i]);
}

__global__ __launch_bounds__(256) void transpose_kernel(
    const float* __restrict__ in, float* __restrict__ out)
{
    __shared__ float tile[32][33];
    const int b = blockIdx.z;
    const int r0 = blockIdx.y * 32, c0 = blockIdx.x * 32;
    const size_t base = (size_t)b * 1024 * 1024;
#pragma unroll
    for (int i = threadIdx.y; i < 32; i += 8)
        tile[i][threadIdx.x] = in[base + (size_t)(r0 + i) * 1024 + c0 + threadIdx.x];
    __syncthreads();
#pragma unroll
    for (int i = threadIdx.y; i < 32; i += 8)
        out[base + (size_t)(c0 + i) * 1024 + r0 + threadIdx.x] = tile[threadIdx.x][i];
}

// ---------------------------------------------------------------------------
// host side
// ---------------------------------------------------------------------------
static const int SMEM256 = 3 * (128 * 80 + 256 * 80);
static const int SMEM128 = 3 * (128 * 80 + 128 * 80);

struct Bufs {
    float *dtb, *xdbl, *xpart, *res1, *hmix, *outm;
    __half *xzh, *xh16, *y16, *dth, *mix16, *wh;
};

// weights pre-converted at wbase offsets
static void run_mamba(const Bufs& B, const float* const* P, const __half* wbase,
                      float* out)
{
    const float* conv_w = P[1];
    const float* conv_b = P[2];
    const float* dt_b   = P[5];
    const float* A_log  = P[6];
    const float* Dp     = P[7];

    gemm_cp<256, 0, 1><<<dim3(2 * DI_ / 256, ROWS / 128, 1), 256, SMEM256>>>(
        B.mix16, DM, wbase + W_IN, nullptr, B.xzh, ROWS, 2 * DI_, DM, DM);

    conv_silu_kernel<<<(ROWS * DI_ / 2) / 256, 256>>>(B.xzh, conv_w, conv_b, B.xh16);

    gemm_cp<128, 0, 0><<<dim3(1, ROWS / 128, KSP), 256, SMEM128>>>(
        B.xh16, DI_, wbase + W_XP, nullptr, B.xpart, ROWS, XD, DI_, DI_ / KSP);
    reduce_xproj_kernel<<<(ROWS * XD) / 256, 256>>>(B.xpart, B.xdbl, B.dth);

    gemm_cp<256, 1, 0><<<dim3(DI_ / 256, ROWS / 128, 1), 256, SMEM256>>>(
        B.dth, DTR, wbase + W_DT, dt_b, B.dtb, ROWS, DI_, DTR, DTR);

    scan_kernel<<<dim3(DI_ / 32, BSZ), 32>>>(B.dtb, B.xh16, B.xdbl, B.xzh,
                                             A_log, Dp, B.y16);

    gemm_cp<256, 0, 0><<<dim3(DM / 256, ROWS / 128, 1), 256, SMEM256>>>(
        B.y16, DI_, wbase + W_OUT, nullptr, out, ROWS, DM, DI_, DI_);
}

extern "C" void kernel_launch(void* const* d_in, const int* in_sizes, int n_in,
                              void* d_out, int out_size)
{
    cudaFuncSetAttribute(gemm_cp<256, 0, 1>, cudaFuncAttributeMaxDynamicSharedMemorySize, SMEM256);
    cudaFuncSetAttribute(gemm_cp<256, 0, 0>, cudaFuncAttributeMaxDynamicSharedMemorySize, SMEM256);
    cudaFuncSetAttribute(gemm_cp<256, 1, 0>, cudaFuncAttributeMaxDynamicSharedMemorySize, SMEM256);
    cudaFuncSetAttribute(gemm_cp<128, 0, 0>, cudaFuncAttributeMaxDynamicSharedMemorySize, SMEM128);

    const float* hstm     = (const float*)d_in[0];
    const float* hscm     = (const float*)d_in[1];
    const float* residual = (const float*)d_in[2];
    const float* norm_tm  = (const float*)d_in[3];
    const float* wavg_tm  = (const float*)d_in[4];

    const float *norm_cm, *wavg_cm;
    int btm;
    const int bcm = 16;
    if (in_sizes[5] == 1024) {            // dict order
        norm_cm = (const float*)d_in[5];
        wavg_cm = (const float*)d_in[6];
        btm = 7;
    } else {                              // signature order
        btm = 5;
        norm_cm = (const float*)d_in[14];
        wavg_cm = (const float*)d_in[15];
    }
    const float* P_tm[9];
    const float* P_cm[9];
    for (int i = 0; i < 9; i++) {
        P_tm[i] = (const float*)d_in[btm + i];
        P_cm[i] = (const float*)d_in[bcm + i];
    }

    Bufs B;
    cudaGetSymbolAddress((void**)&B.dtb,   g_dt);
    cudaGetSymbolAddress((void**)&B.xdbl,  g_xdbl);
    cudaGetSymbolAddress((void**)&B.xpart, g_xpart);
    cudaGetSymbolAddress((void**)&B.res1,  g_res1);
    cudaGetSymbolAddress((void**)&B.hmix,  g_hmix);
    cudaGetSymbolAddress((void**)&B.outm,  g_outm);
    cudaGetSymbolAddress((void**)&B.xzh,   g_xzh);
    cudaGetSymbolAddress((void**)&B.xh16,  g_xh16);
    cudaGetSymbolAddress((void**)&B.y16,   g_y16);
    cudaGetSymbolAddress((void**)&B.dth,   g_dth);
    cudaGetSymbolAddress((void**)&B.mix16, g_mix16);
    cudaGetSymbolAddress((void**)&B.wh,    g_wh);

    // one fused weight conversion launch (both paths)
    W8 segs;
    segs.s[0] = { P_tm[0], B.wh + W_IN,               2 * DI_ * DM };
    segs.s[1] = { P_tm[3], B.wh + W_XP,               XD * DI_ };
    segs.s[2] = { P_tm[4], B.wh + W_DT,               DI_ * DTR };
    segs.s[3] = { P_tm[8], B.wh + W_OUT,              DM * DI_ };
    segs.s[4] = { P_cm[0], B.wh + W_STRIDE + W_IN,    2 * DI_ * DM };
    segs.s[5] = { P_cm[3], B.wh + W_STRIDE + W_XP,    XD * DI_ };
    segs.s[6] = { P_cm[4], B.wh + W_STRIDE + W_DT,    DI_ * DTR };
    segs.s[7] = { P_cm[8], B.wh + W_STRIDE + W_OUT,   DM * DI_ };
    convert_all_kernel<<<2048, 256>>>(segs);

    float* dout = (float*)d_out;
    const long total = (long)BSZ * SEQ * DM;
    float* res2_out = (out_size >= 2 * total) ? (dout + total) : B.res1;

    // --- token-mixer path ---
    rms_mix_tm_kernel<<<ROWS, 256>>>(residual, hstm, hscm, norm_tm, wavg_tm,
                                     B.res1, B.mix16);
    run_mamba(B, P_tm, B.wh, B.outm);

    // --- channel-mixer path ---
    rms_mix_cm_kernel<<<ROWS, 256>>>(B.res1, B.outm, hstm, hscm, norm_cm, wavg_cm,
                                     res2_out, B.hmix);
    transpose_h_kernel<<<dim3(32, 32, BSZ), dim3(32, 8)>>>(B.hmix, B.mix16);
    run_mamba(B, P_cm, B.wh + W_STRIDE, B.outm);
    transpose_kernel<<<dim3(32, 32, BSZ), dim3(32, 8)>>>(B.outm, dout);
}

// round 8
// speedup vs baseline: 2.5261x; 1.5163x over previous
#include <cuda_runtime.h>
#include <cuda_fp16.h>
#include <cstdint>
#include <math.h>

// ---------------------------------------------------------------------------
// SambaMixerBlock: B=8, S=D=1024, N=16, DCONV=4, EXPAND=2 -> DI=2048, DT_RANK=64
// Round 8: scan prefetch queues were spilling to LOCAL MEMORY (runtime-indexed
//          arrays in an unrolled-less loop) -> explicit unroll-by-4 puts them
//          in registers. dt tensor now fp16.
// ---------------------------------------------------------------------------

#define BSZ   8
#define SEQ   1024
#define DM    1024
#define DI_   2048
#define NST   16
#define DTR   64
#define XD    96
#define ROWS  (BSZ*SEQ)
#define KSP   4                      // x_proj split-K factor

// fp32 scratch
__device__ float g_xdbl[(size_t)ROWS * XD];
__device__ float g_xpart[(size_t)KSP * ROWS * XD];
__device__ float g_res1[(size_t)ROWS * DM];
__device__ float g_hmix[(size_t)ROWS * DM];
__device__ float g_outm[(size_t)ROWS * DM];
// fp16 scratch
__device__ __half g_xzh [(size_t)ROWS * 2 * DI_];
__device__ __half g_xh16[(size_t)ROWS * DI_];
__device__ __half g_y16 [(size_t)ROWS * DI_];
__device__ __half g_dtb16[(size_t)ROWS * DI_];
__device__ __half g_dth [(size_t)ROWS * DTR];
__device__ __half g_mix16[(size_t)ROWS * DM];

// converted weights: per path IN | XPROJ | DT | OUT
#define W_IN   0
#define W_XP   (2 * DI_ * DM)
#define W_DT   (W_XP + XD * DI_)
#define W_OUT  (W_DT + DI_ * DTR)
#define W_STRIDE (W_OUT + DM * DI_)
__device__ __half g_wh[(size_t)2 * W_STRIDE];

// ---------------------------------------------------------------------------
__device__ __forceinline__ void cpa16(uint32_t d, const void* s)
{
    asm volatile("cp.async.cg.shared.global [%0], [%1], 16;" :: "r"(d), "l"(s));
}
__device__ __forceinline__ void cpa16z(uint32_t d, const void* s, bool ok)
{
    int sz = ok ? 16 : 0;
    asm volatile("cp.async.cg.shared.global [%0], [%1], 16, %2;"
                 :: "r"(d), "l"(s), "r"(sz));
}
#define CP_COMMIT() asm volatile("cp.async.commit_group;" ::: "memory")
#define CP_WAIT1()  asm volatile("cp.async.wait_group 1;" ::: "memory")

__device__ __forceinline__ void mma16816(float* d, const uint32_t* a, const uint32_t* b)
{
    asm volatile(
        "mma.sync.aligned.m16n8k16.row.col.f32.f16.f16.f32 "
        "{%0,%1,%2,%3}, {%4,%5,%6,%7}, {%8,%9}, {%0,%1,%2,%3};"
        : "+f"(d[0]), "+f"(d[1]), "+f"(d[2]), "+f"(d[3])
        : "r"(a[0]), "r"(a[1]), "r"(a[2]), "r"(a[3]), "r"(b[0]), "r"(b[1]));
}

__device__ __forceinline__ void ldmx4(uint32_t* r, uint32_t addr)
{
    asm volatile("ldmatrix.sync.aligned.m8n8.x4.shared.b16 {%0,%1,%2,%3}, [%4];"
                 : "=r"(r[0]), "=r"(r[1]), "=r"(r[2]), "=r"(r[3]) : "r"(addr));
}

// ---------------------------------------------------------------------------
// Pipelined HMMA GEMM: C = A(M,K) * B(N,K)^T, fp16 in, fp32 acc.
// CTA 128 x TN, BK=32, 3-stage cp.async, ldmatrix. 80B row stride.
// EPI: 1 = softplus(C + bias). OUTH: 1 = fp16 C.
// ---------------------------------------------------------------------------
template<int TN, int EPI, int OUTH>
__global__ __launch_bounds__(256, 1) void gemm_cp(
    const __half* __restrict__ A, int lda,
    const __half* __restrict__ Bm,
    const float* __restrict__ bias, void* __restrict__ Cbase,
    int M, int Nsz, int Kfull, int Ksub)
{
    constexpr int ABY = 128 * 80;
    constexpr int BBY = TN * 80;
    constexpr int STG = ABY + BBY;
    constexpr int JN  = TN / 32;

    extern __shared__ __align__(16) char smem[];
    const uint32_t sb0 = (uint32_t)__cvta_generic_to_shared(smem);

    const int tid = threadIdx.x, wid = tid >> 5, lid = tid & 31;
    const int bm = blockIdx.y * 128, bn = blockIdx.x * TN;
    const int koff = blockIdx.z * Ksub;
    const int wm = (wid & 1) * 64, wn = (wid >> 1) * (TN / 4);
    const int g = lid >> 2, t4 = lid & 3;
    const int S = Ksub >> 5;

    const int lr = lid & 7, tq = lid >> 3;
    const int a_ro = (tq & 1) * 8, a_co = (tq >> 1) * 16;
    const int b_ro = (tq >> 1) * 8, b_co = (tq & 1) * 16;

    auto issue = [&](int s) {
        const int k0 = koff + (s << 5);
        const uint32_t st = sb0 + (s % 3) * STG;
#pragma unroll
        for (int i = 0; i < 2; i++) {
            const int id = tid + i * 256, row = id >> 2, q = id & 3;
            const size_t go = (size_t)(bm + row) * lda + k0 + q * 8;
            cpa16(st + row * 80 + q * 16, A + go);
        }
#pragma unroll
        for (int i = 0; i < TN / 64; i++) {
            const int id = tid + i * 256, row = id >> 2, q = id & 3;
            const bool ok = (bn + row) < Nsz;
            const int r2 = ok ? (bn + row) : 0;
            const size_t go = (size_t)r2 * Kfull + k0 + q * 8;
            cpa16z(st + ABY + row * 80 + q * 16, Bm + go, ok);
        }
    };

    float acc[4][JN][4];
#pragma unroll
    for (int i = 0; i < 4; i++)
#pragma unroll
        for (int j = 0; j < JN; j++)
#pragma unroll
            for (int c = 0; c < 4; c++) acc[i][j][c] = 0.f;

    issue(0); CP_COMMIT();
    if (S > 1) issue(1);
    CP_COMMIT();

    for (int s = 0; s < S; s++) {
        CP_WAIT1();
        __syncthreads();
        if (s + 2 < S) issue(s + 2);
        CP_COMMIT();

        const uint32_t st = sb0 + (s % 3) * STG;
#pragma unroll
        for (int kk = 0; kk < 2; kk++) {
            const int cb = kk * 32;
            uint32_t ah[4][4];
#pragma unroll
            for (int i = 0; i < 4; i++)
                ldmx4(ah[i], st + (wm + i * 16 + a_ro + lr) * 80 + cb + a_co);
#pragma unroll
            for (int j2 = 0; j2 < JN / 2; j2++) {
                uint32_t bh[4];
                ldmx4(bh, st + ABY + (wn + j2 * 16 + b_ro + lr) * 80 + cb + b_co);
#pragma unroll
                for (int i = 0; i < 4; i++) {
                    mma16816(acc[i][2 * j2],     ah[i], bh);
                    mma16816(acc[i][2 * j2 + 1], ah[i], bh + 2);
                }
            }
        }
    }

#pragma unroll
    for (int i = 0; i < 4; i++) {
        const int r0 = bm + wm + i * 16 + g;
#pragma unroll
        for (int j = 0; j < JN; j++) {
            const int c = bn + wn + j * 8 + t4 * 2;
            if (c < Nsz) {
                float v0 = acc[i][j][0], v1 = acc[i][j][1];
                float v2 = acc[i][j][2], v3 = acc[i][j][3];
                if (EPI == 1) {
                    const float b0 = bias[c], b1 = bias[c + 1];
                    v0 += b0; v1 += b1; v2 += b0; v3 += b1;
                    v0 = (v0 > 20.f) ? v0 : log1pf(__expf(v0));
                    v1 = (v1 > 20.f) ? v1 : log1pf(__expf(v1));
                    v2 = (v2 > 20.f) ? v2 : log1pf(__expf(v2));
                    v3 = (v3 > 20.f) ? v3 : log1pf(__expf(v3));
                }
                if (OUTH) {
                    __half* C = (__half*)Cbase + (size_t)blockIdx.z * M * Nsz;
                    *(__half2*)(C + (size_t)r0 * Nsz + c) = __floats2half2_rn(v0, v1);
                    *(__half2*)(C + (size_t)(r0 + 8) * Nsz + c) = __floats2half2_rn(v2, v3);
                } else {
                    float* C = (float*)Cbase + (size_t)blockIdx.z * M * Nsz;
                    *(float2*)(C + (size_t)r0 * Nsz + c)       = make_float2(v0, v1);
                    *(float2*)(C + (size_t)(r0 + 8) * Nsz + c) = make_float2(v2, v3);
                }
            }
        }
    }
}

// ---------------------------------------------------------------------------
struct WSeg { const float* src; __half* dst; int n; };
struct W8   { WSeg s[8]; };

__global__ __launch_bounds__(256) void convert_all_kernel(W8 segs)
{
    const int stride = gridDim.x * 256;
    const int t0 = blockIdx.x * 256 + threadIdx.x;
#pragma unroll
    for (int k = 0; k < 8; k++) {
        const float* src = segs.s[k].src;
        __half* dst = segs.s[k].dst;
        const int n = segs.s[k].n;
        for (int i = t0; i < n; i += stride)
            dst[i] = __float2half_rn(src[i]);
    }
}

__global__ __launch_bounds__(256) void reduce_xproj_kernel(
    const float* __restrict__ part, float* __restrict__ xdbl,
    __half* __restrict__ dth)
{
    const size_t n1 = (size_t)ROWS * XD;
    const size_t i = (size_t)blockIdx.x * 256 + threadIdx.x;
    float s = part[i] + part[i + n1] + part[i + 2 * n1] + part[i + 3 * n1];
    xdbl[i] = s;
    const int col = (int)(i % XD);
    if (col < DTR) dth[(i / XD) * DTR + col] = __float2half_rn(s);
}

// ---------------------------------------------------------------------------
// Depthwise causal conv + bias + SiLU, 2 channels/thread (half2)
// ---------------------------------------------------------------------------
__global__ __launch_bounds__(256) void conv_silu_kernel(
    const __half* __restrict__ xz, const float* __restrict__ w,
    const float* __restrict__ bias, __half* __restrict__ xh)
{
    const long i = (long)blockIdx.x * 256 + threadIdx.x;
    const int  d2 = (int)(i & (DI_ / 2 - 1));
    const int  d  = d2 * 2;
    const long bl = i >> 10;
    const int  l = (int)(bl & (SEQ - 1));
    const long b = bl >> 10;

    const __half* base = xz + ((size_t)b * SEQ) * (2 * DI_) + d;
    const float2 bs = *(const float2*)(bias + d);
    float a0 = bs.x, a1 = bs.y;
    const float4 wa = *(const float4*)(w + d * 4);
    const float4 wb = *(const float4*)(w + d * 4 + 4);

    __half2 v;
    float2 f;
    if (l >= 3) { v = *(const __half2*)(base + (size_t)(l - 3) * (2 * DI_));
                  f = __half22float2(v); a0 += wa.x * f.x; a1 += wb.x * f.y; }
    if (l >= 2) { v = *(const __half2*)(base + (size_t)(l - 2) * (2 * DI_));
                  f = __half22float2(v); a0 += wa.y * f.x; a1 += wb.y * f.y; }
    if (l >= 1) { v = *(const __half2*)(base + (size_t)(l - 1) * (2 * DI_));
                  f = __half22float2(v); a0 += wa.z * f.x; a1 += wb.z * f.y; }
    v = *(const __half2*)(base + (size_t)l * (2 * DI_));
    f = __half22float2(v); a0 += wa.w * f.x; a1 += wb.w * f.y;

    a0 = a0 / (1.f + __expf(-a0));
    a1 = a1 / (1.f + __expf(-a1));
    *(__half2*)(xh + bl * DI_ + d) = __floats2half2_rn(a0, a1);
}

// ---------------------------------------------------------------------------
// Selective scan: 1 warp/block, register prefetch queues via EXPLICIT
// unroll-by-4 (compile-time slot indices -> no local-memory spill).
// ---------------------------------------------------------------------------
__global__ __launch_bounds__(32) void scan_kernel(
    const __half* __restrict__ dtb, const __half* __restrict__ xh,
    const float* __restrict__ xdbl, const __half* __restrict__ xz,
    const float* __restrict__ A_log, const float* __restrict__ Dp,
    __half* __restrict__ y)
{
    const int b = blockIdx.y;
    const int lane = threadIdx.x;
    const int d = blockIdx.x * 32 + lane;

    float A[NST], h[NST];
#pragma unroll
    for (int n = 0; n < NST; n++) {
        A[n] = -__expf(A_log[d * NST + n]);
        h[n] = 0.f;
    }
    const float A0 = A[0];
    bool uni = true;
#pragma unroll
    for (int n = 1; n < NST; n++)
        uni = uni && (fabsf(A[n] - (n + 1) * A0) <= 1e-3f * (n + 1) * fabsf(A0) + 1e-12f);
    const float dval = Dp[d];

    const size_t rowbase = (size_t)b * SEQ;

    // 4-deep register queues (explicit scalars via unrolled prologue)
    __half dq[4], xq[4], zq[4];
    float bcq[4];
#pragma unroll
    for (int p = 0; p < 4; p++) {
        const size_t idx = (rowbase + p) * DI_ + d;
        dq[p]  = dtb[idx];
        xq[p]  = xh[idx];
        zq[p]  = xz[(rowbase + p) * (2 * DI_) + DI_ + d];
        bcq[p] = xdbl[(rowbase + p) * XD + DTR + lane];
    }

    for (int l0 = 0; l0 < SEQ; l0 += 4) {
#pragma unroll
        for (int p = 0; p < 4; p++) {                    // compile-time p
            const int l = l0 + p;
            const float dtv = __half2float(dq[p]);
            const float xv  = __half2float(xq[p]);
            const float zv  = __half2float(zq[p]);
            const float bcv = bcq[p];

            // prefetch l+4 into slot p (constant index -> stays in registers)
            const int lp = (l + 4 < SEQ) ? l + 4 : SEQ - 1;
            const size_t idx2 = (rowbase + lp) * DI_ + d;
            dq[p]  = dtb[idx2];
            xq[p]  = xh[idx2];
            zq[p]  = xz[(rowbase + lp) * (2 * DI_) + DI_ + d];
            bcq[p] = xdbl[(rowbase + lp) * XD + DTR + lane];

            const float dx = dtv * xv;
            float acc = 0.f;
            if (uni) {
                const float p1 = __expf(dtv * A0);
                float e[NST];
                e[0] = p1;
                e[1] = p1 * p1;
                e[2] = e[1] * p1;
                e[3] = e[1] * e[1];
#pragma unroll
                for (int n = 4; n < NST; n++) e[n] = e[n - 4] * e[3];
#pragma unroll
                for (int n = 0; n < NST; n++) {
                    const float Bn = __shfl_sync(0xffffffffu, bcv, n);
                    const float Cn = __shfl_sync(0xffffffffu, bcv, 16 + n);
                    h[n] = e[n] * h[n] + dx * Bn;
                    acc += h[n] * Cn;
                }
            } else {
#pragma unroll
                for (int n = 0; n < NST; n++) {
                    const float Bn = __shfl_sync(0xffffffffu, bcv, n);
                    const float Cn = __shfl_sync(0xffffffffu, bcv, 16 + n);
                    h[n] = __expf(dtv * A[n]) * h[n] + dx * Bn;
                    acc += h[n] * Cn;
                }
            }
            acc += xv * dval;
            acc *= zv / (1.f + __expf(-zv));
            y[(rowbase + l) * DI_ + d] = __float2half_rn(acc);
        }
    }
}

// ---------------------------------------------------------------------------
__device__ __forceinline__ float block_sum256(float v)
{
    __shared__ float red[8];
    const int lane = threadIdx.x & 31, w = threadIdx.x >> 5;
#pragma unroll
    for (int o = 16; o; o >>= 1) v += __shfl_xor_sync(0xffffffffu, v, o);
    if (!lane) red[w] = v;
    __syncthreads();
    if (w == 0) {
        v = (lane < 8) ? red[lane] : 0.f;
#pragma unroll
        for (int o = 4; o; o >>= 1) v += __shfl_xor_sync(0xffffffffu, v, o);
        if (!lane) red[0] = v;
    }
    __syncthreads();
    return red[0];
}

__global__ __launch_bounds__(256) void rms_mix_tm_kernel(
    const float* __restrict__ residual, const float* __restrict__ hstm,
    const float* __restrict__ hscm, const float* __restrict__ nw,
    const float* __restrict__ wavg, float* __restrict__ res1,
    __half* __restrict__ omix)
{
    const int bs = blockIdx.x, b = bs >> 10, s = bs & 1023, t = threadIdx.x;
    const size_t r4 = (size_t)bs * 256 + t;
    const size_t i0 = ((size_t)(b * 2 + 0) * 1024 + s) * 256 + t;
    const size_t i1 = ((size_t)(b * 2 + 1) * 1024 + s) * 256 + t;

    float4 r  = ((const float4*)residual)[r4];
    float4 c1 = ((const float4*)hscm)[i1];
    r.x += c1.x; r.y += c1.y; r.z += c1.z; r.w += c1.w;
    ((float4*)res1)[r4] = r;

    const float tot = block_sum256(r.x * r.x + r.y * r.y + r.z * r.z + r.w * r.w);
    const float scale = rsqrtf(tot * (1.f / (float)DM) + 1e-5f);

    float w0 = wavg[s], w1 = wavg[1024 + s], w2 = wavg[2048 + s], w3 = wavg[3072 + s];
    const float mx = fmaxf(fmaxf(w0, w1), fmaxf(w2, w3));
    w0 = __expf(w0 - mx); w1 = __expf(w1 - mx); w2 = __expf(w2 - mx); w3 = __expf(w3 - mx);
    const float inv = 1.f / (w0 + w1 + w2 + w3);
    w0 *= inv; w1 *= inv; w2 *= inv; w3 *= inv;

    const float4 a0 = ((const float4*)hstm)[i0];
    const float4 a1 = ((const float4*)hstm)[i1];
    const float4 c0 = ((const float4*)hscm)[i0];
    const float4 wn = ((const float4*)nw)[t];
    float o0 = w0 * a0.x + w1 * a1.x + w2 * c0.x + w3 * (r.x * scale * wn.x);
    float o1 = w0 * a0.y + w1 * a1.y + w2 * c0.y + w3 * (r.y * scale * wn.y);
    float o2 = w0 * a0.z + w1 * a1.z + w2 * c0.z + w3 * (r.z * scale * wn.z);
    float o3 = w0 * a0.w + w1 * a1.w + w2 * c0.w + w3 * (r.w * scale * wn.w);
    __half2* op = (__half2*)(omix + r4 * 4);
    op[0] = __floats2half2_rn(o0, o1);
    op[1] = __floats2half2_rn(o2, o3);
}

__global__ __launch_bounds__(256) void rms_mix_cm_kernel(
    const float* __restrict__ res1, const float* __restrict__ outm,
    const float* __restrict__ hstm, const float* __restrict__ hscm,
    const float* __restrict__ nw, const float* __restrict__ wavg,
    float* __restrict__ res2, float* __restrict__ hmix)
{
    const int bs = blockIdx.x, b = bs >> 10, s = bs & 1023, t = threadIdx.x;
    const size_t r4 = (size_t)bs * 256 + t;
    const size_t i0 = ((size_t)(b * 2 + 0) * 1024 + s) * 256 + t;
    const size_t i1 = ((size_t)(b * 2 + 1) * 1024 + s) * 256 + t;

    float4 r  = ((const float4*)res1)[r4];
    float4 om = ((const float4*)outm)[r4];
    r.x += om.x; r.y += om.y; r.z += om.z; r.w += om.w;
    ((float4*)res2)[r4] = r;

    const float tot = block_sum256(r.x * r.x + r.y * r.y + r.z * r.z + r.w * r.w);
    const float scale = rsqrtf(tot * (1.f / (float)DM) + 1e-5f);

    float w[5];
#pragma unroll
    for (int n = 0; n < 5; n++) w[n] = wavg[n * 1024 + s];
    float mx = w[0];
#pragma unroll
    for (int n = 1; n < 5; n++) mx = fmaxf(mx, w[n]);
    float sum = 0.f;
#pragma unroll
    for (int n = 0; n < 5; n++) { w[n] = __expf(w[n] - mx); sum += w[n]; }
    const float inv = 1.f / sum;
#pragma unroll
    for (int n = 0; n < 5; n++) w[n] *= inv;

    const float4 a0 = ((const float4*)hstm)[i0];
    const float4 a1 = ((const float4*)hstm)[i1];
    const float4 c0 = ((const float4*)hscm)[i0];
    const float4 c1 = ((const float4*)hscm)[i1];
    const float4 wn = ((const float4*)nw)[t];
    float4 o;
    o.x = w[0]*a0.x + w[1]*a1.x + w[2]*(r.x*scale*wn.x) + w[3]*c0.x + w[4]*c1.x;
    o.y = w[0]*a0.y + w[1]*a1.y + w[2]*(r.y*scale*wn.y) + w[3]*c0.y + w[4]*c1.y;
    o.z = w[0]*a0.z + w[1]*a1.z + w[2]*(r.z*scale*wn.z) + w[3]*c0.z + w[4]*c1.z;
    o.w = w[0]*a0.w + w[1]*a1.w + w[2]*(r.w*scale*wn.w) + w[3]*c0.w + w[4]*c1.w;
    ((float4*)hmix)[r4] = o;
}

__global__ __launch_bounds__(256) void transpose_h_kernel(
    const float* __restrict__ in, __half* __restrict__ o)
{
    __shared__ float tile[32][33];
    const int b = blockIdx.z;
    const int r0 = blockIdx.y * 32, c0 = blockIdx.x * 32;
    const size_t base = (size_t)b * 1024 * 1024;
#pragma unroll
    for (int i = threadIdx.y; i < 32; i += 8)
        tile[i][threadIdx.x] = in[base + (size_t)(r0 + i) * 1024 + c0 + threadIdx.x];
    __syncthreads();
#pragma unroll
    for (int i = threadIdx.y; i < 32; i += 8)
        o[base + (size_t)(c0 + i) * 1024 + r0 + threadIdx.x] =
            __float2half_rn(tile[threadIdx.x][i]);
}

__global__ __launch_bounds__(256) void transpose_kernel(
    const float* __restrict__ in, float* __restrict__ out)
{
    __shared__ float tile[32][33];
    const int b = blockIdx.z;
    const int r0 = blockIdx.y * 32, c0 = blockIdx.x * 32;
    const size_t base = (size_t)b * 1024 * 1024;
#pragma unroll
    for (int i = threadIdx.y; i < 32; i += 8)
        tile[i][threadIdx.x] = in[base + (size_t)(r0 + i) * 1024 + c0 + threadIdx.x];
    __syncthreads();
#pragma unroll
    for (int i = threadIdx.y; i < 32; i += 8)
        out[base + (size_t)(c0 + i) * 1024 + r0 + threadIdx.x] = tile[threadIdx.x][i];
}

// ---------------------------------------------------------------------------
// host side
// ---------------------------------------------------------------------------
static const int SMEM256 = 3 * (128 * 80 + 256 * 80);
static const int SMEM128 = 3 * (128 * 80 + 128 * 80);

struct Bufs {
    float *xdbl, *xpart, *res1, *hmix, *outm;
    __half *xzh, *xh16, *y16, *dtb16, *dth, *mix16, *wh;
};

static void run_mamba(const Bufs& B, const float* const* P, const __half* wbase,
                      float* out)
{
    const float* conv_w = P[1];
    const float* conv_b = P[2];
    const float* dt_b   = P[5];
    const float* A_log  = P[6];
    const float* Dp     = P[7];

    gemm_cp<256, 0, 1><<<dim3(2 * DI_ / 256, ROWS / 128, 1), 256, SMEM256>>>(
        B.mix16, DM, wbase + W_IN, nullptr, B.xzh, ROWS, 2 * DI_, DM, DM);

    conv_silu_kernel<<<(ROWS * DI_ / 2) / 256, 256>>>(B.xzh, conv_w, conv_b, B.xh16);

    gemm_cp<128, 0, 0><<<dim3(1, ROWS / 128, KSP), 256, SMEM128>>>(
        B.xh16, DI_, wbase + W_XP, nullptr, B.xpart, ROWS, XD, DI_, DI_ / KSP);
    reduce_xproj_kernel<<<(ROWS * XD) / 256, 256>>>(B.xpart, B.xdbl, B.dth);

    gemm_cp<256, 1, 1><<<dim3(DI_ / 256, ROWS / 128, 1), 256, SMEM256>>>(
        B.dth, DTR, wbase + W_DT, dt_b, B.dtb16, ROWS, DI_, DTR, DTR);

    scan_kernel<<<dim3(DI_ / 32, BSZ), 32>>>(B.dtb16, B.xh16, B.xdbl, B.xzh,
                                             A_log, Dp, B.y16);

    gemm_cp<256, 0, 0><<<dim3(DM / 256, ROWS / 128, 1), 256, SMEM256>>>(
        B.y16, DI_, wbase + W_OUT, nullptr, out, ROWS, DM, DI_, DI_);
}

extern "C" void kernel_launch(void* const* d_in, const int* in_sizes, int n_in,
                              void* d_out, int out_size)
{
    cudaFuncSetAttribute(gemm_cp<256, 0, 1>, cudaFuncAttributeMaxDynamicSharedMemorySize, SMEM256);
    cudaFuncSetAttribute(gemm_cp<256, 0, 0>, cudaFuncAttributeMaxDynamicSharedMemorySize, SMEM256);
    cudaFuncSetAttribute(gemm_cp<256, 1, 1>, cudaFuncAttributeMaxDynamicSharedMemorySize, SMEM256);
    cudaFuncSetAttribute(gemm_cp<128, 0, 0>, cudaFuncAttributeMaxDynamicSharedMemorySize, SMEM128);

    const float* hstm     = (const float*)d_in[0];
    const float* hscm     = (const float*)d_in[1];
    const float* residual = (const float*)d_in[2];
    const float* norm_tm  = (const float*)d_in[3];
    const float* wavg_tm  = (const float*)d_in[4];

    const float *norm_cm, *wavg_cm;
    int btm;
    const int bcm = 16;
    if (in_sizes[5] == 1024) {            // dict order
        norm_cm = (const float*)d_in[5];
        wavg_cm = (const float*)d_in[6];
        btm = 7;
    } else {                              // signature order
        btm = 5;
        norm_cm = (const float*)d_in[14];
        wavg_cm = (const float*)d_in[15];
    }
    const float* P_tm[9];
    const float* P_cm[9];
    for (int i = 0; i < 9; i++) {
        P_tm[i] = (const float*)d_in[btm + i];
        P_cm[i] = (const float*)d_in[bcm + i];
    }

    Bufs B;
    cudaGetSymbolAddress((void**)&B.xdbl,  g_xdbl);
    cudaGetSymbolAddress((void**)&B.xpart, g_xpart);
    cudaGetSymbolAddress((void**)&B.res1,  g_res1);
    cudaGetSymbolAddress((void**)&B.hmix,  g_hmix);
    cudaGetSymbolAddress((void**)&B.outm,  g_outm);
    cudaGetSymbolAddress((void**)&B.xzh,   g_xzh);
    cudaGetSymbolAddress((void**)&B.xh16,  g_xh16);
    cudaGetSymbolAddress((void**)&B.y16,   g_y16);
    cudaGetSymbolAddress((void**)&B.dtb16, g_dtb16);
    cudaGetSymbolAddress((void**)&B.dth,   g_dth);
    cudaGetSymbolAddress((void**)&B.mix16, g_mix16);
    cudaGetSymbolAddress((void**)&B.wh,    g_wh);

    // one fused weight conversion launch (both paths)
    W8 segs;
    segs.s[0] = { P_tm[0], B.wh + W_IN,               2 * DI_ * DM };
    segs.s[1] = { P_tm[3], B.wh + W_XP,               XD * DI_ };
    segs.s[2] = { P_tm[4], B.wh + W_DT,               DI_ * DTR };
    segs.s[3] = { P_tm[8], B.wh + W_OUT,              DM * DI_ };
    segs.s[4] = { P_cm[0], B.wh + W_STRIDE + W_IN,    2 * DI_ * DM };
    segs.s[5] = { P_cm[3], B.wh + W_STRIDE + W_XP,    XD * DI_ };
    segs.s[6] = { P_cm[4], B.wh + W_STRIDE + W_DT,    DI_ * DTR };
    segs.s[7] = { P_cm[8], B.wh + W_STRIDE + W_OUT,   DM * DI_ };
    convert_all_kernel<<<2048, 256>>>(segs);

    float* dout = (float*)d_out;
    const long total = (long)BSZ * SEQ * DM;
    float* res2_out = (out_size >= 2 * total) ? (dout + total) : B.res1;

    // --- token-mixer path ---
    rms_mix_tm_kernel<<<ROWS, 256>>>(residual, hstm, hscm, norm_tm, wavg_tm,
                                     B.res1, B.mix16);
    run_mamba(B, P_tm, B.wh, B.outm);

    // --- channel-mixer path ---
    rms_mix_cm_kernel<<<ROWS, 256>>>(B.res1, B.outm, hstm, hscm, norm_cm, wavg_cm,
                                     res2_out, B.hmix);
    transpose_h_kernel<<<dim3(32, 32, BSZ), dim3(32, 8)>>>(B.hmix, B.mix16);
    run_mamba(B, P_cm, B.wh + W_STRIDE, B.outm);
    transpose_kernel<<<dim3(32, 32, BSZ), dim3(32, 8)>>>(B.outm, dout);
}

// round 10
// speedup vs baseline: 2.7759x; 1.0989x over previous
#include <cuda_runtime.h>
#include <cuda_fp16.h>
#include <cstdint>
#include <math.h>

// ---------------------------------------------------------------------------
// SambaMixerBlock: B=8, S=D=1024, N=16, DCONV=4, EXPAND=2 -> DI=2048, DT_RANK=64
// Round 10: round-9 occupancy experiment with the B-tile fill bug fixed
//           (128-row B tile needs 512 cp.asyncs; round 9 issued only 256).
// ---------------------------------------------------------------------------

#define BSZ   8
#define SEQ   1024
#define DM    1024
#define DI_   2048
#define NST   16
#define DTR   64
#define XD    96
#define ROWS  (BSZ*SEQ)
#define KSP   4                      // x_proj split-K factor

// fp32 scratch
__device__ float g_xdbl[(size_t)ROWS * XD];
__device__ float g_xpart[(size_t)KSP * ROWS * XD];
__device__ float g_res1[(size_t)ROWS * DM];
__device__ float g_hmix[(size_t)ROWS * DM];
__device__ float g_outm[(size_t)ROWS * DM];
// fp16 scratch
__device__ __half g_xzh [(size_t)ROWS * 2 * DI_];
__device__ __half g_xh16[(size_t)ROWS * DI_];
__device__ __half g_y16 [(size_t)ROWS * DI_];
__device__ __half g_dtb16[(size_t)ROWS * DI_];
__device__ __half g_dth [(size_t)ROWS * DTR];
__device__ __half g_mix16[(size_t)ROWS * DM];

// converted weights: per path IN | XPROJ | DT | OUT
#define W_IN   0
#define W_XP   (2 * DI_ * DM)
#define W_DT   (W_XP + XD * DI_)
#define W_OUT  (W_DT + DI_ * DTR)
#define W_STRIDE (W_OUT + DM * DI_)
__device__ __half g_wh[(size_t)2 * W_STRIDE];

// ---------------------------------------------------------------------------
__device__ __forceinline__ void cpa16(uint32_t d, const void* s)
{
    asm volatile("cp.async.cg.shared.global [%0], [%1], 16;" :: "r"(d), "l"(s));
}
__device__ __forceinline__ void cpa16z(uint32_t d, const void* s, bool ok)
{
    int sz = ok ? 16 : 0;
    asm volatile("cp.async.cg.shared.global [%0], [%1], 16, %2;"
                 :: "r"(d), "l"(s), "r"(sz));
}
#define CP_COMMIT() asm volatile("cp.async.commit_group;" ::: "memory")
#define CP_WAIT1()  asm volatile("cp.async.wait_group 1;" ::: "memory")

__device__ __forceinline__ void mma16816(float* d, const uint32_t* a, const uint32_t* b)
{
    asm volatile(
        "mma.sync.aligned.m16n8k16.row.col.f32.f16.f16.f32 "
        "{%0,%1,%2,%3}, {%4,%5,%6,%7}, {%8,%9}, {%0,%1,%2,%3};"
        : "+f"(d[0]), "+f"(d[1]), "+f"(d[2]), "+f"(d[3])
        : "r"(a[0]), "r"(a[1]), "r"(a[2]), "r"(a[3]), "r"(b[0]), "r"(b[1]));
}

__device__ __forceinline__ void ldmx4(uint32_t* r, uint32_t addr)
{
    asm volatile("ldmatrix.sync.aligned.m8n8.x4.shared.b16 {%0,%1,%2,%3}, [%4];"
                 : "=r"(r[0]), "=r"(r[1]), "=r"(r[2]), "=r"(r[3]) : "r"(addr));
}

// ---------------------------------------------------------------------------
// Pipelined HMMA GEMM: C = A(M,K) * B(N,K)^T, fp16 in, fp32 acc.
// CTA 128 x 128, 8 warps (warp tile 64x32), BK=32, 3-stage cp.async,
// ldmatrix, 80B row stride. 2 CTAs/SM.
// EPI: 1 = softplus(C + bias). OUTH: 1 = fp16 C.
// ---------------------------------------------------------------------------
template<int EPI, int OUTH>
__global__ __launch_bounds__(256, 2) void gemm_cp(
    const __half* __restrict__ A, int lda,
    const __half* __restrict__ Bm,
    const float* __restrict__ bias, void* __restrict__ Cbase,
    int M, int Nsz, int Kfull, int Ksub)
{
    constexpr int TN  = 128;
    constexpr int ABY = 128 * 80;
    constexpr int BBY = TN * 80;
    constexpr int STG = ABY + BBY;
    constexpr int JN  = TN / 32;          // 4

    extern __shared__ __align__(16) char smem[];
    const uint32_t sb0 = (uint32_t)__cvta_generic_to_shared(smem);

    const int tid = threadIdx.x, wid = tid >> 5, lid = tid & 31;
    const int bm = blockIdx.y * 128, bn = blockIdx.x * TN;
    const int koff = blockIdx.z * Ksub;
    const int wm = (wid & 1) * 64, wn = (wid >> 1) * 32;
    const int g = lid >> 2, t4 = lid & 3;
    const int S = Ksub >> 5;

    const int lr = lid & 7, tq = lid >> 3;
    const int a_ro = (tq & 1) * 8, a_co = (tq >> 1) * 16;
    const int b_ro = (tq >> 1) * 8, b_co = (tq & 1) * 16;

    auto issue = [&](int s) {
        const int k0 = koff + (s << 5);
        const uint32_t st = sb0 + (s % 3) * STG;
#pragma unroll
        for (int i = 0; i < 2; i++) {
            const int id = tid + i * 256, row = id >> 2, q = id & 3;
            const size_t go = (size_t)(bm + row) * lda + k0 + q * 8;
            cpa16(st + row * 80 + q * 16, A + go);
        }
#pragma unroll
        for (int i = 0; i < 2; i++) {                  // FIX: 128 rows x 4 chunks
            const int id = tid + i * 256, row = id >> 2, q = id & 3;
            const bool ok = (bn + row) < Nsz;
            const int r2 = ok ? (bn + row) : 0;
            const size_t go = (size_t)r2 * Kfull + k0 + q * 8;
            cpa16z(st + ABY + row * 80 + q * 16, Bm + go, ok);
        }
    };

    float acc[4][JN][4];
#pragma unroll
    for (int i = 0; i < 4; i++)
#pragma unroll
        for (int j = 0; j < JN; j++)
#pragma unroll
            for (int c = 0; c < 4; c++) acc[i][j][c] = 0.f;

    issue(0); CP_COMMIT();
    if (S > 1) issue(1);
    CP_COMMIT();

    for (int s = 0; s < S; s++) {
        CP_WAIT1();
        __syncthreads();
        if (s + 2 < S) issue(s + 2);
        CP_COMMIT();

        const uint32_t st = sb0 + (s % 3) * STG;
#pragma unroll
        for (int kk = 0; kk < 2; kk++) {
            const int cb = kk * 32;
            uint32_t ah[4][4];
#pragma unroll
            for (int i = 0; i < 4; i++)
                ldmx4(ah[i], st + (wm + i * 16 + a_ro + lr) * 80 + cb + a_co);
#pragma unroll
            for (int j2 = 0; j2 < JN / 2; j2++) {
                uint32_t bh[4];
                ldmx4(bh, st + ABY + (wn + j2 * 16 + b_ro + lr) * 80 + cb + b_co);
#pragma unroll
                for (int i = 0; i < 4; i++) {
                    mma16816(acc[i][2 * j2],     ah[i], bh);
                    mma16816(acc[i][2 * j2 + 1], ah[i], bh + 2);
                }
            }
        }
    }

#pragma unroll
    for (int i = 0; i < 4; i++) {
        const int r0 = bm + wm + i * 16 + g;
#pragma unroll
        for (int j = 0; j < JN; j++) {
            const int c = bn + wn + j * 8 + t4 * 2;
            if (c < Nsz) {
                float v0 = acc[i][j][0], v1 = acc[i][j][1];
                float v2 = acc[i][j][2], v3 = acc[i][j][3];
                if (EPI == 1) {
                    const float b0 = bias[c], b1 = bias[c + 1];
                    v0 += b0; v1 += b1; v2 += b0; v3 += b1;
                    v0 = (v0 > 20.f) ? v0 : __logf(1.f + __expf(v0));
                    v1 = (v1 > 20.f) ? v1 : __logf(1.f + __expf(v1));
                    v2 = (v2 > 20.f) ? v2 : __logf(1.f + __expf(v2));
                    v3 = (v3 > 20.f) ? v3 : __logf(1.f + __expf(v3));
                }
                if (OUTH) {
                    __half* C = (__half*)Cbase + (size_t)blockIdx.z * M * Nsz;
                    *(__half2*)(C + (size_t)r0 * Nsz + c) = __floats2half2_rn(v0, v1);
                    *(__half2*)(C + (size_t)(r0 + 8) * Nsz + c) = __floats2half2_rn(v2, v3);
                } else {
                    float* C = (float*)Cbase + (size_t)blockIdx.z * M * Nsz;
                    *(float2*)(C + (size_t)r0 * Nsz + c)       = make_float2(v0, v1);
                    *(float2*)(C + (size_t)(r0 + 8) * Nsz + c) = make_float2(v2, v3);
                }
            }
        }
    }
}

// ---------------------------------------------------------------------------
struct WSeg { const float* src; __half* dst; int n; };
struct W8   { WSeg s[8]; };

__global__ __launch_bounds__(256) void convert_all_kernel(W8 segs)
{
    const int stride = gridDim.x * 256;
    const int t0 = blockIdx.x * 256 + threadIdx.x;
#pragma unroll
    for (int k = 0; k < 8; k++) {
        const float* src = segs.s[k].src;
        __half* dst = segs.s[k].dst;
        const int n = segs.s[k].n;
        for (int i = t0; i < n; i += stride)
            dst[i] = __float2half_rn(src[i]);
    }
}

__global__ __launch_bounds__(256) void reduce_xproj_kernel(
    const float* __restrict__ part, float* __restrict__ xdbl,
    __half* __restrict__ dth)
{
    const size_t n1 = (size_t)ROWS * XD;
    const size_t i = (size_t)blockIdx.x * 256 + threadIdx.x;
    float s = part[i] + part[i + n1] + part[i + 2 * n1] + part[i + 3 * n1];
    xdbl[i] = s;
    const int col = (int)(i % XD);
    if (col < DTR) dth[(i / XD) * DTR + col] = __float2half_rn(s);
}

// ---------------------------------------------------------------------------
// Depthwise causal conv + bias + SiLU, 2 channels/thread (half2)
// ---------------------------------------------------------------------------
__global__ __launch_bounds__(256) void conv_silu_kernel(
    const __half* __restrict__ xz, const float* __restrict__ w,
    const float* __restrict__ bias, __half* __restrict__ xh)
{
    const long i = (long)blockIdx.x * 256 + threadIdx.x;
    const int  d2 = (int)(i & (DI_ / 2 - 1));
    const int  d  = d2 * 2;
    const long bl = i >> 10;
    const int  l = (int)(bl & (SEQ - 1));
    const long b = bl >> 10;

    const __half* base = xz + ((size_t)b * SEQ) * (2 * DI_) + d;
    const float2 bs = *(const float2*)(bias + d);
    float a0 = bs.x, a1 = bs.y;
    const float4 wa = *(const float4*)(w + d * 4);
    const float4 wb = *(const float4*)(w + d * 4 + 4);

    __half2 v;
    float2 f;
    if (l >= 3) { v = *(const __half2*)(base + (size_t)(l - 3) * (2 * DI_));
                  f = __half22float2(v); a0 += wa.x * f.x; a1 += wb.x * f.y; }
    if (l >= 2) { v = *(const __half2*)(base + (size_t)(l - 2) * (2 * DI_));
                  f = __half22float2(v); a0 += wa.y * f.x; a1 += wb.y * f.y; }
    if (l >= 1) { v = *(const __half2*)(base + (size_t)(l - 1) * (2 * DI_));
                  f = __half22float2(v); a0 += wa.z * f.x; a1 += wb.z * f.y; }
    v = *(const __half2*)(base + (size_t)l * (2 * DI_));
    f = __half22float2(v); a0 += wa.w * f.x; a1 += wb.w * f.y;

    a0 = a0 / (1.f + __expf(-a0));
    a1 = a1 / (1.f + __expf(-a1));
    *(__half2*)(xh + bl * DI_ + d) = __floats2half2_rn(a0, a1);
}

// ---------------------------------------------------------------------------
// Selective scan: 1 warp/block, register queues via explicit unroll-by-4.
// ---------------------------------------------------------------------------
__global__ __launch_bounds__(32) void scan_kernel(
    const __half* __restrict__ dtb, const __half* __restrict__ xh,
    const float* __restrict__ xdbl, const __half* __restrict__ xz,
    const float* __restrict__ A_log, const float* __restrict__ Dp,
    __half* __restrict__ y)
{
    const int b = blockIdx.y;
    const int lane = threadIdx.x;
    const int d = blockIdx.x * 32 + lane;

    float A[NST], h[NST];
#pragma unroll
    for (int n = 0; n < NST; n++) {
        A[n] = -__expf(A_log[d * NST + n]);
        h[n] = 0.f;
    }
    const float A0 = A[0];
    bool uni = true;
#pragma unroll
    for (int n = 1; n < NST; n++)
        uni = uni && (fabsf(A[n] - (n + 1) * A0) <= 1e-3f * (n + 1) * fabsf(A0) + 1e-12f);
    const float dval = Dp[d];

    const size_t rowbase = (size_t)b * SEQ;

    __half dq[4], xq[4], zq[4];
    float bcq[4];
#pragma unroll
    for (int p = 0; p < 4; p++) {
        const size_t idx = (rowbase + p) * DI_ + d;
        dq[p]  = dtb[idx];
        xq[p]  = xh[idx];
        zq[p]  = xz[(rowbase + p) * (2 * DI_) + DI_ + d];
        bcq[p] = xdbl[(rowbase + p) * XD + DTR + lane];
    }

    for (int l0 = 0; l0 < SEQ; l0 += 4) {
#pragma unroll
        for (int p = 0; p < 4; p++) {
            const int l = l0 + p;
            const float dtv = __half2float(dq[p]);
            const float xv  = __half2float(xq[p]);
            const float zv  = __half2float(zq[p]);
            const float bcv = bcq[p];

            const int lp = (l + 4 < SEQ) ? l + 4 : SEQ - 1;
            const size_t idx2 = (rowbase + lp) * DI_ + d;
            dq[p]  = dtb[idx2];
            xq[p]  = xh[idx2];
            zq[p]  = xz[(rowbase + lp) * (2 * DI_) + DI_ + d];
            bcq[p] = xdbl[(rowbase + lp) * XD + DTR + lane];

            const float dx = dtv * xv;
            float acc = 0.f;
            if (uni) {
                const float p1 = __expf(dtv * A0);
                float e[NST];
                e[0] = p1;
                e[1] = p1 * p1;
                e[2] = e[1] * p1;
                e[3] = e[1] * e[1];
#pragma unroll
                for (int n = 4; n < NST; n++) e[n] = e[n - 4] * e[3];
#pragma unroll
                for (int n = 0; n < NST; n++) {
                    const float Bn = __shfl_sync(0xffffffffu, bcv, n);
                    const float Cn = __shfl_sync(0xffffffffu, bcv, 16 + n);
                    h[n] = e[n] * h[n] + dx * Bn;
                    acc += h[n] * Cn;
                }
            } else {
#pragma unroll
                for (int n = 0; n < NST; n++) {
                    const float Bn = __shfl_sync(0xffffffffu, bcv, n);
                    const float Cn = __shfl_sync(0xffffffffu, bcv, 16 + n);
                    h[n] = __expf(dtv * A[n]) * h[n] + dx * Bn;
                    acc += h[n] * Cn;
                }
            }
            acc += xv * dval;
            acc *= zv / (1.f + __expf(-zv));
            y[(rowbase + l) * DI_ + d] = __float2half_rn(acc);
        }
    }
}

// ---------------------------------------------------------------------------
__device__ __forceinline__ float block_sum256(float v)
{
    __shared__ float red[8];
    const int lane = threadIdx.x & 31, w = threadIdx.x >> 5;
#pragma unroll
    for (int o = 16; o; o >>= 1) v += __shfl_xor_sync(0xffffffffu, v, o);
    if (!lane) red[w] = v;
    __syncthreads();
    if (w == 0) {
        v = (lane < 8) ? red[lane] : 0.f;
#pragma unroll
        for (int o = 4; o; o >>= 1) v += __shfl_xor_sync(0xffffffffu, v, o);
        if (!lane) red[0] = v;
    }
    __syncthreads();
    return red[0];
}

__global__ __launch_bounds__(256) void rms_mix_tm_kernel(
    const float* __restrict__ residual, const float* __restrict__ hstm,
    const float* __restrict__ hscm, const float* __restrict__ nw,
    const float* __restrict__ wavg, float* __restrict__ res1,
    __half* __restrict__ omix)
{
    const int bs = blockIdx.x, b = bs >> 10, s = bs & 1023, t = threadIdx.x;
    const size_t r4 = (size_t)bs * 256 + t;
    const size_t i0 = ((size_t)(b * 2 + 0) * 1024 + s) * 256 + t;
    const size_t i1 = ((size_t)(b * 2 + 1) * 1024 + s) * 256 + t;

    float4 r  = ((const float4*)residual)[r4];
    float4 c1 = ((const float4*)hscm)[i1];
    r.x += c1.x; r.y += c1.y; r.z += c1.z; r.w += c1.w;
    ((float4*)res1)[r4] = r;

    const float tot = block_sum256(r.x * r.x + r.y * r.y + r.z * r.z + r.w * r.w);
    const float scale = rsqrtf(tot * (1.f / (float)DM) + 1e-5f);

    float w0 = wavg[s], w1 = wavg[1024 + s], w2 = wavg[2048 + s], w3 = wavg[3072 + s];
    const float mx = fmaxf(fmaxf(w0, w1), fmaxf(w2, w3));
    w0 = __expf(w0 - mx); w1 = __expf(w1 - mx); w2 = __expf(w2 - mx); w3 = __expf(w3 - mx);
    const float inv = 1.f / (w0 + w1 + w2 + w3);
    w0 *= inv; w1 *= inv; w2 *= inv; w3 *= inv;

    const float4 a0 = ((const float4*)hstm)[i0];
    const float4 a1 = ((const float4*)hstm)[i1];
    const float4 c0 = ((const float4*)hscm)[i0];
    const float4 wn = ((const float4*)nw)[t];
    float o0 = w0 * a0.x + w1 * a1.x + w2 * c0.x + w3 * (r.x * scale * wn.x);
    float o1 = w0 * a0.y + w1 * a1.y + w2 * c0.y + w3 * (r.y * scale * wn.y);
    float o2 = w0 * a0.z + w1 * a1.z + w2 * c0.z + w3 * (r.z * scale * wn.z);
    float o3 = w0 * a0.w + w1 * a1.w + w2 * c0.w + w3 * (r.w * scale * wn.w);
    __half2* op = (__half2*)(omix + r4 * 4);
    op[0] = __floats2half2_rn(o0, o1);
    op[1] = __floats2half2_rn(o2, o3);
}

__global__ __launch_bounds__(256) void rms_mix_cm_kernel(
    const float* __restrict__ res1, const float* __restrict__ outm,
    const float* __restrict__ hstm, const float* __restrict__ hscm,
    const float* __restrict__ nw, const float* __restrict__ wavg,
    float* __restrict__ res2, float* __restrict__ hmix)
{
    const int bs = blockIdx.x, b = bs >> 10, s = bs & 1023, t = threadIdx.x;
    const size_t r4 = (size_t)bs * 256 + t;
    const size_t i0 = ((size_t)(b * 2 + 0) * 1024 + s) * 256 + t;
    const size_t i1 = ((size_t)(b * 2 + 1) * 1024 + s) * 256 + t;

    float4 r  = ((const float4*)res1)[r4];
    float4 om = ((const float4*)outm)[r4];
    r.x += om.x; r.y += om.y; r.z += om.z; r.w += om.w;
    ((float4*)res2)[r4] = r;

    const float tot = block_sum256(r.x * r.x + r.y * r.y + r.z * r.z + r.w * r.w);
    const float scale = rsqrtf(tot * (1.f / (float)DM) + 1e-5f);

    float w[5];
#pragma unroll
    for (int n = 0; n < 5; n++) w[n] = wavg[n * 1024 + s];
    float mx = w[0];
#pragma unroll
    for (int n = 1; n < 5; n++) mx = fmaxf(mx, w[n]);
    float sum = 0.f;
#pragma unroll
    for (int n = 0; n < 5; n++) { w[n] = __expf(w[n] - mx); sum += w[n]; }
    const float inv = 1.f / sum;
#pragma unroll
    for (int n = 0; n < 5; n++) w[n] *= inv;

    const float4 a0 = ((const float4*)hstm)[i0];
    const float4 a1 = ((const float4*)hstm)[i1];
    const float4 c0 = ((const float4*)hscm)[i0];
    const float4 c1 = ((const float4*)hscm)[i1];
    const float4 wn = ((const float4*)nw)[t];
    float4 o;
    o.x = w[0]*a0.x + w[1]*a1.x + w[2]*(r.x*scale*wn.x) + w[3]*c0.x + w[4]*c1.x;
    o.y = w[0]*a0.y + w[1]*a1.y + w[2]*(r.y*scale*wn.y) + w[3]*c0.y + w[4]*c1.y;
    o.z = w[0]*a0.z + w[1]*a1.z + w[2]*(r.z*scale*wn.z) + w[3]*c0.z + w[4]*c1.z;
    o.w = w[0]*a0.w + w[1]*a1.w + w[2]*(r.w*scale*wn.w) + w[3]*c0.w + w[4]*c1.w;
    ((float4*)hmix)[r4] = o;
}

__global__ __launch_bounds__(256) void transpose_h_kernel(
    const float* __restrict__ in, __half* __restrict__ o)
{
    __shared__ float tile[32][33];
    const int b = blockIdx.z;
    const int r0 = blockIdx.y * 32, c0 = blockIdx.x * 32;
    const size_t base = (size_t)b * 1024 * 1024;
#pragma unroll
    for (int i = threadIdx.y; i < 32; i += 8)
        tile[i][threadIdx.x] = in[base + (size_t)(r0 + i) * 1024 + c0 + threadIdx.x];
    __syncthreads();
#pragma unroll
    for (int i = threadIdx.y; i < 32; i += 8)
        o[base + (size_t)(c0 + i) * 1024 + r0 + threadIdx.x] =
            __float2half_rn(tile[threadIdx.x][i]);
}

__global__ __launch_bounds__(256) void transpose_kernel(
    const float* __restrict__ in, float* __restrict__ out)
{
    __shared__ float tile[32][33];
    const int b = blockIdx.z;
    const int r0 = blockIdx.y * 32, c0 = blockIdx.x * 32;
    const size_t base = (size_t)b * 1024 * 1024;
#pragma unroll
    for (int i = threadIdx.y; i < 32; i += 8)
        tile[i][threadIdx.x] = in[base + (size_t)(r0 + i) * 1024 + c0 + threadIdx.x];
    __syncthreads();
#pragma unroll
    for (int i = threadIdx.y; i < 32; i += 8)
        out[base + (size_t)(c0 + i) * 1024 + r0 + threadIdx.x] = tile[threadIdx.x][i];
}

// ---------------------------------------------------------------------------
// host side
// ---------------------------------------------------------------------------
static const int SMEMG = 3 * (128 * 80 + 128 * 80);   // 61440 per CTA

struct Bufs {
    float *xdbl, *xpart, *res1, *hmix, *outm;
    __half *xzh, *xh16, *y16, *dtb16, *dth, *mix16, *wh;
};

static void run_mamba(const Bufs& B, const float* const* P, const __half* wbase,
                      float* out)
{
    const float* conv_w = P[1];
    const float* conv_b = P[2];
    const float* dt_b   = P[5];
    const float* A_log  = P[6];
    const float* Dp     = P[7];

    gemm_cp<0, 1><<<dim3(2 * DI_ / 128, ROWS / 128, 1), 256, SMEMG>>>(
        B.mix16, DM, wbase + W_IN, nullptr, B.xzh, ROWS, 2 * DI_, DM, DM);

    conv_silu_kernel<<<(ROWS * DI_ / 2) / 256, 256>>>(B.xzh, conv_w, conv_b, B.xh16);

    gemm_cp<0, 0><<<dim3(1, ROWS / 128, KSP), 256, SMEMG>>>(
        B.xh16, DI_, wbase + W_XP, nullptr, B.xpart, ROWS, XD, DI_, DI_ / KSP);
    reduce_xproj_kernel<<<(ROWS * XD) / 256, 256>>>(B.xpart, B.xdbl, B.dth);

    gemm_cp<1, 1><<<dim3(DI_ / 128, ROWS / 128, 1), 256, SMEMG>>>(
        B.dth, DTR, wbase + W_DT, dt_b, B.dtb16, ROWS, DI_, DTR, DTR);

    scan_kernel<<<dim3(DI_ / 32, BSZ), 32>>>(B.dtb16, B.xh16, B.xdbl, B.xzh,
                                             A_log, Dp, B.y16);

    gemm_cp<0, 0><<<dim3(DM / 128, ROWS / 128, 1), 256, SMEMG>>>(
        B.y16, DI_, wbase + W_OUT, nullptr, out, ROWS, DM, DI_, DI_);
}

extern "C" void kernel_launch(void* const* d_in, const int* in_sizes, int n_in,
                              void* d_out, int out_size)
{
    cudaFuncSetAttribute(gemm_cp<0, 1>, cudaFuncAttributeMaxDynamicSharedMemorySize, SMEMG);
    cudaFuncSetAttribute(gemm_cp<0, 0>, cudaFuncAttributeMaxDynamicSharedMemorySize, SMEMG);
    cudaFuncSetAttribute(gemm_cp<1, 1>, cudaFuncAttributeMaxDynamicSharedMemorySize, SMEMG);

    const float* hstm     = (const float*)d_in[0];
    const float* hscm     = (const float*)d_in[1];
    const float* residual = (const float*)d_in[2];
    const float* norm_tm  = (const float*)d_in[3];
    const float* wavg_tm  = (const float*)d_in[4];

    const float *norm_cm, *wavg_cm;
    int btm;
    const int bcm = 16;
    if (in_sizes[5] == 1024) {            // dict order
        norm_cm = (const float*)d_in[5];
        wavg_cm = (const float*)d_in[6];
        btm = 7;
    } else {                              // signature order
        btm = 5;
        norm_cm = (const float*)d_in[14];
        wavg_cm = (const float*)d_in[15];
    }
    const float* P_tm[9];
    const float* P_cm[9];
    for (int i = 0; i < 9; i++) {
        P_tm[i] = (const float*)d_in[btm + i];
        P_cm[i] = (const float*)d_in[bcm + i];
    }

    Bufs B;
    cudaGetSymbolAddress((void**)&B.xdbl,  g_xdbl);
    cudaGetSymbolAddress((void**)&B.xpart, g_xpart);
    cudaGetSymbolAddress((void**)&B.res1,  g_res1);
    cudaGetSymbolAddress((void**)&B.hmix,  g_hmix);
    cudaGetSymbolAddress((void**)&B.outm,  g_outm);
    cudaGetSymbolAddress((void**)&B.xzh,   g_xzh);
    cudaGetSymbolAddress((void**)&B.xh16,  g_xh16);
    cudaGetSymbolAddress((void**)&B.y16,   g_y16);
    cudaGetSymbolAddress((void**)&B.dtb16, g_dtb16);
    cudaGetSymbolAddress((void**)&B.dth,   g_dth);
    cudaGetSymbolAddress((void**)&B.mix16, g_mix16);
    cudaGetSymbolAddress((void**)&B.wh,    g_wh);

    // one fused weight conversion launch (both paths)
    W8 segs;
    segs.s[0] = { P_tm[0], B.wh + W_IN,               2 * DI_ * DM };
    segs.s[1] = { P_tm[3], B.wh + W_XP,               XD * DI_ };
    segs.s[2] = { P_tm[4], B.wh + W_DT,               DI_ * DTR };
    segs.s[3] = { P_tm[8], B.wh + W_OUT,              DM * DI_ };
    segs.s[4] = { P_cm[0], B.wh + W_STRIDE + W_IN,    2 * DI_ * DM };
    segs.s[5] = { P_cm[3], B.wh + W_STRIDE + W_XP,    XD * DI_ };
    segs.s[6] = { P_cm[4], B.wh + W_STRIDE + W_DT,    DI_ * DTR };
    segs.s[7] = { P_cm[8], B.wh + W_STRIDE + W_OUT,   DM * DI_ };
    convert_all_kernel<<<2048, 256>>>(segs);

    float* dout = (float*)d_out;
    const long total = (long)BSZ * SEQ * DM;
    float* res2_out = (out_size >= 2 * total) ? (dout + total) : B.res1;

    // --- token-mixer path ---
    rms_mix_tm_kernel<<<ROWS, 256>>>(residual, hstm, hscm, norm_tm, wavg_tm,
                                     B.res1, B.mix16);
    run_mamba(B, P_tm, B.wh, B.outm);

    // --- channel-mixer path ---
    rms_mix_cm_kernel<<<ROWS, 256>>>(B.res1, B.outm, hstm, hscm, norm_cm, wavg_cm,
                                     res2_out, B.hmix);
    transpose_h_kernel<<<dim3(32, 32, BSZ), dim3(32, 8)>>>(B.hmix, B.mix16);
    run_mamba(B, P_cm, B.wh + W_STRIDE, B.outm);
    transpose_kernel<<<dim3(32, 32, BSZ), dim3(32, 8)>>>(B.outm, dout);
}